// round 2
// baseline (speedup 1.0000x reference)
#include <cuda_runtime.h>
#include <cuda_bf16.h>

// CIN (xDeepFM) on GB300.
// m = b*32 + d flattening (M = 512*32 = 16384).
// Layer l:  Hnext[m,n] = sum_{i<40, j<Fi} X[m,i] * Hprev[m,j] * W[(i*Fi+j), n]
// Final:    out[b, no] = sum_d H_layer(no/200)[(b*32+d), no%200]
//
// Implemented as a fused "generated-A" fp32 GEMM: A[m,(i,j)] = X[m,i]*H[m,j]
// is built from small smem tiles; W streamed through smem in (i, j-chunk) order.

constexpr int M_TOTAL = 16384;   // 512 * 32
constexpr int F0      = 40;
constexpr int NSZ     = 200;
constexpr int BATCH   = 512;
constexpr int DDIM    = 32;

// scratch (static device globals: allocation-free)
__device__ float g_X [M_TOTAL * F0];
__device__ float g_H1[M_TOTAL * NSZ];
__device__ float g_H2[M_TOTAL * NSZ];
__device__ float g_H3[M_TOTAL * NSZ];

// ---------------------------------------------------------------------------
// X[m,i] = inputs[b, i, d]  with m = b*32 + d   (inputs: [512, 40, 32] f32)
// ---------------------------------------------------------------------------
__global__ void transpose_x_kernel(const float* __restrict__ inp) {
    int idx = blockIdx.x * blockDim.x + threadIdx.x;
    if (idx >= M_TOTAL * F0) return;
    int m = idx / F0;
    int i = idx - m * F0;
    int b = m >> 5;
    int d = m & 31;
    g_X[idx] = inp[b * (F0 * DDIM) + i * DDIM + d];
}

// ---------------------------------------------------------------------------
// One CIN layer. Grid: 256 blocks of BM=64 rows. 128 threads.
// Thread layout: tn = tid&7 (8 n-groups, TN=25), tm = tid>>3 (16 m-groups, TM=4).
// smem: xs[64][41], hs[64][FI+1], ws[KJ][200]  (dynamic)
// ---------------------------------------------------------------------------
template <int FI, int KJ>
__global__ __launch_bounds__(128)
void cin_layer_kernel(const float* __restrict__ Hprev,
                      const float* __restrict__ W,
                      float* __restrict__ Hnext) {
    constexpr int BM  = 64;
    constexpr int TM  = 4;
    constexpr int TN  = 25;
    constexpr int NTH = 128;
    constexpr int XS_STRIDE = F0 + 1;   // 41, avoid bank conflicts
    constexpr int HS_STRIDE = FI + 1;

    extern __shared__ float sm[];
    float* xs = sm;                               // BM * XS_STRIDE
    float* hs = xs + BM * XS_STRIDE;              // BM * HS_STRIDE
    float* ws = hs + BM * HS_STRIDE;              // KJ * NSZ

    const int tid = threadIdx.x;
    const int tn  = tid & 7;
    const int tm  = tid >> 3;                     // 0..15
    const int m0  = blockIdx.x * BM;

    // load X tile (coalesced from g_X)
    for (int idx = tid; idx < BM * F0; idx += NTH) {
        int ml = idx / F0;
        int i  = idx - ml * F0;
        xs[ml * XS_STRIDE + i] = g_X[(m0 + ml) * F0 + i];
    }
    // load H tile (coalesced)
    for (int idx = tid; idx < BM * FI; idx += NTH) {
        int ml = idx / FI;
        int j  = idx - ml * FI;
        hs[ml * HS_STRIDE + j] = Hprev[(m0 + ml) * FI + j];
    }
    __syncthreads();

    float acc[TM][TN];
#pragma unroll
    for (int r = 0; r < TM; ++r)
#pragma unroll
        for (int c = 0; c < TN; ++c) acc[r][c] = 0.0f;

    for (int i = 0; i < F0; ++i) {
        float xr[TM];
#pragma unroll
        for (int r = 0; r < TM; ++r)
            xr[r] = xs[(tm * TM + r) * XS_STRIDE + i];

        for (int j0 = 0; j0 < FI; j0 += KJ) {
            __syncthreads();   // previous ws chunk fully consumed
            // W rows for fixed i are contiguous: (i*FI + j0)*200 + t
            const float* wsrc = W + (i * FI + j0) * NSZ;
            for (int t = tid; t < KJ * NSZ; t += NTH)
                ws[t] = wsrc[t];
            __syncthreads();

#pragma unroll 4
            for (int jj = 0; jj < KJ; ++jj) {
                float a[TM];
#pragma unroll
                for (int r = 0; r < TM; ++r)
                    a[r] = xr[r] * hs[(tm * TM + r) * HS_STRIDE + j0 + jj];
#pragma unroll
                for (int c = 0; c < TN; ++c) {
                    float w = ws[jj * NSZ + tn * TN + c];
#pragma unroll
                    for (int r = 0; r < TM; ++r)
                        acc[r][c] = fmaf(a[r], w, acc[r][c]);
                }
            }
        }
    }

    // epilogue
#pragma unroll
    for (int r = 0; r < TM; ++r) {
        float* dst = Hnext + (m0 + tm * TM + r) * NSZ + tn * TN;
#pragma unroll
        for (int c = 0; c < TN; ++c) dst[c] = acc[r][c];
    }
}

// ---------------------------------------------------------------------------
// out[b, no] = sum_d H_layer[(b*32+d), no%200]
// ---------------------------------------------------------------------------
__global__ void reduce_out_kernel(float* __restrict__ out) {
    int idx = blockIdx.x * blockDim.x + threadIdx.x;
    if (idx >= BATCH * 3 * NSZ) return;
    int b  = idx / (3 * NSZ);
    int no = idx - b * (3 * NSZ);
    const float* H = (no < NSZ) ? g_H1 : (no < 2 * NSZ ? g_H2 : g_H3);
    int n = no % NSZ;
    const float* p = H + (b * DDIM) * NSZ + n;
    float s = 0.0f;
#pragma unroll
    for (int d = 0; d < DDIM; ++d) s += p[d * NSZ];
    out[idx] = s;
}

// ---------------------------------------------------------------------------
extern "C" void kernel_launch(void* const* d_in, const int* in_sizes, int n_in,
                              void* d_out, int out_size) {
    const float* inp = (const float*)d_in[0];
    const float* W0  = (const float*)d_in[1];
    const float* W1  = (const float*)d_in[2];
    const float* W2  = (const float*)d_in[3];
    float* out = (float*)d_out;

    void *pX, *pH1, *pH2, *pH3;
    cudaGetSymbolAddress(&pX,  g_X);
    cudaGetSymbolAddress(&pH1, g_H1);
    cudaGetSymbolAddress(&pH2, g_H2);
    cudaGetSymbolAddress(&pH3, g_H3);
    float* X  = (float*)pX;
    float* H1 = (float*)pH1;
    float* H2 = (float*)pH2;
    float* H3 = (float*)pH3;

    constexpr int KJ40  = 8;    // 40 % 8  == 0
    constexpr int KJ200 = 20;   // 200 % 20 == 0
    const int smem40  = (64 * 41 + 64 * 41  + KJ40  * NSZ) * 4;   // 27,392 B
    const int smem200 = (64 * 41 + 64 * 201 + KJ200 * NSZ) * 4;   // 77,952 B

    cudaFuncSetAttribute(cin_layer_kernel<200, KJ200>,
                         cudaFuncAttributeMaxDynamicSharedMemorySize, smem200);

    transpose_x_kernel<<<(M_TOTAL * F0 + 255) / 256, 256>>>(inp);

    cin_layer_kernel<40,  KJ40 ><<<M_TOTAL / 64, 128, smem40 >>>(X,  W0, H1);
    cin_layer_kernel<200, KJ200><<<M_TOTAL / 64, 128, smem200>>>(H1, W1, H2);
    cin_layer_kernel<200, KJ200><<<M_TOTAL / 64, 128, smem200>>>(H2, W2, H3);

    reduce_out_kernel<<<(BATCH * 3 * NSZ + 255) / 256, 256>>>(out);
}

// round 4
// speedup vs baseline: 5.3799x; 5.3799x over previous
#include <cuda_runtime.h>
#include <cstdint>

// ===========================================================================
// CIN (xDeepFM) on GB300 via legacy mma.sync tf32 (sm_80+ path — the PTX
// toolchain here targets compute_103 without the 'a' suffix, so tcgen05 is
// unavailable; mma.sync.m16n8k8.tf32 still runs on the tensor cores).
//
// m = b*32 + d (M = 16384).  Hnext[m,n] = sum_{i,j} X[m,i] Hprev[m,j] W[i*FI+j, n]
// Single GEMM with generated A:  A[m, k=j*40+i] = X[m,i] * Hprev[m,j]
// K reordered as (j outer, i inner): a 40-wide chunk has fixed j, so
// A fragments come from a resident x-tile and one h-column per chunk.
// W is pre-packed (prep kernel) into per-chunk, per-lane fragment-major
// blobs, tf32-rounded (cvt.rna), streamed via cp.async 3-stage pipeline.
// ===========================================================================

constexpr int MT  = 16384;  // 512*32
constexpr int NSZ = 200;
constexpr int F0  = 40;

// per-(chunk,ns) blob: [nw(2)][lane(32)][78 floats] = 19968 B
constexpr int BLOB_NS_BYTES  = 2 * 32 * 78 * 4;          // 19968
constexpr int BLOB_CH_FLOATS = 2 * 2 * 32 * 78;          // 9984 per chunk

__device__ float g_Xt [F0  * MT];
__device__ float g_Ht1[NSZ * MT];
__device__ float g_Ht2[NSZ * MT];
__device__ float g_Ht3[NSZ * MT];
__device__ __align__(16) float g_B0[40  * BLOB_CH_FLOATS];   // 1.6 MB
__device__ __align__(16) float g_B1[200 * BLOB_CH_FLOATS];   // 8 MB
__device__ __align__(16) float g_B2[200 * BLOB_CH_FLOATS];   // 8 MB

// ---------------------------------------------------------------- helpers
__device__ __forceinline__ uint32_t smem_u32(const void* p) {
    uint32_t a;
    asm("{ .reg .u64 t; cvta.to.shared.u64 t, %1; cvt.u32.u64 %0, t; }"
        : "=r"(a) : "l"(p));
    return a;
}

__device__ __forceinline__ uint32_t f2tf32(float x) {
    uint32_t u;
    asm("cvt.rna.tf32.f32 %0, %1;" : "=r"(u) : "f"(x));
    return u;
}

__device__ __forceinline__ void cp16(uint32_t dst_smem, const void* src) {
    asm volatile("cp.async.cg.shared.global [%0], [%1], 16;"
                 :: "r"(dst_smem), "l"(src) : "memory");
}

__device__ __forceinline__ void mma8(float* d,
                                     uint32_t a0, uint32_t a1, uint32_t a2, uint32_t a3,
                                     uint32_t b0, uint32_t b1) {
    asm volatile(
        "mma.sync.aligned.m16n8k8.row.col.f32.tf32.tf32.f32 "
        "{%0,%1,%2,%3}, {%4,%5,%6,%7}, {%8,%9}, {%0,%1,%2,%3};"
        : "+f"(d[0]), "+f"(d[1]), "+f"(d[2]), "+f"(d[3])
        : "r"(a0), "r"(a1), "r"(a2), "r"(a3), "r"(b0), "r"(b1));
}

// ---------------------------------------------------------------- prep kernels
// Xt[i][m] = inputs[b, i, d], m = b*32+d
__global__ void transpose_x_kernel(const float* __restrict__ inp) {
    int idx = blockIdx.x * blockDim.x + threadIdx.x;
    if (idx >= F0 * MT) return;
    int i = idx >> 14;
    int m = idx & (MT - 1);
    int b = m >> 5, d = m & 31;
    g_Xt[idx] = inp[b * (F0 * 32) + i * 32 + d];
}

// Pack W into fragment-major blob, tf32-rounded.
// blob[j][ns][nw][lane][v]:  v<70: nt=v/10, r=v%10, ks=r/2, p=r&1
//   i = ks*8 + (lane&3) + p*4 ;  n = ns*112 + nw*56 + nt*8 + (lane>>2)
//   value = W[(i*FI + j)*200 + n]  (0 if n>=200 or v>=70)
__global__ void prep_blob_kernel(const float* __restrict__ W,
                                 float* __restrict__ blob, int FI, int CH) {
    int idx = blockIdx.x * blockDim.x + threadIdx.x;
    if (idx >= CH * BLOB_CH_FLOATS) return;
    int v    = idx % 78;
    int rest = idx / 78;
    int lane = rest & 31; rest >>= 5;
    int nw   = rest & 1;  rest >>= 1;
    int ns   = rest & 1;
    int j    = rest >> 1;
    float val = 0.0f;
    if (v < 70) {
        int nt = v / 10, r = v - nt * 10;
        int ks = r >> 1, p = r & 1;
        int i  = ks * 8 + (lane & 3) + p * 4;
        int n  = ns * 112 + nw * 56 + nt * 8 + (lane >> 2);
        if (n < 200) val = W[((size_t)i * FI + j) * 200 + n];
    }
    blob[idx] = __uint_as_float(f2tf32(val));
}

// ---------------------------------------------------------------- layer kernel
// grid = 256 CTAs: (bx>>1) = m-block of 128 rows, (bx&1) = n-split (112 cols).
// 256 threads = 8 warps: wm = wid&3 (32 m each), wn = wid>>2 (56 n each).
// smem: bbuf 3*19968 B | xs 40*136*4 B | hb 3*128*4 B  = 83200 B
template <int CH>
__global__ __launch_bounds__(256, 2)
void cin_mma_layer(const float* __restrict__ Hprev,   // [CH][MT]
                   const float* __restrict__ blob,
                   float* __restrict__ Hout)          // [200][MT]
{
    extern __shared__ __align__(16) char smem[];
    float* bbuf = (float*)smem;                         // 3 * 4992 floats
    float* xs   = (float*)(smem + 59904);               // 40 * 136
    float* hb   = (float*)(smem + 59904 + 21760);       // 3 * 128

    const int tid  = threadIdx.x;
    const int lane = tid & 31;
    const int wid  = tid >> 5;
    const int wm   = wid & 3;
    const int wn   = wid >> 2;
    const int g    = lane >> 2;
    const int t4   = lane & 3;
    const int m0   = (blockIdx.x >> 1) * 128;
    const int ns   = blockIdx.x & 1;

    // x tile: xs[i*136 + m] (stride 136 words -> conflict-free frag reads)
    for (int idx = tid; idx < 40 * 128; idx += 256) {
        int i = idx >> 7, m = idx & 127;
        xs[i * 136 + m] = g_Xt[i * MT + m0 + m];
    }

    const uint32_t uB = smem_u32(bbuf);
    const uint32_t uH = smem_u32(hb);

    auto issue = [&](int c, int s) {
        const char* srcB = (const char*)blob + ((size_t)c * 2 + ns) * BLOB_NS_BYTES;
        uint32_t dB = uB + s * BLOB_NS_BYTES;
        for (int t = tid * 16; t < BLOB_NS_BYTES; t += 256 * 16)
            cp16(dB + t, srcB + t);
        if (tid < 32)
            cp16(uH + s * 512 + tid * 16,
                 (const char*)(Hprev + (size_t)c * MT + m0) + tid * 16);
    };

    issue(0, 0);
    asm volatile("cp.async.commit_group;" ::: "memory");
    issue(1, 1);
    asm volatile("cp.async.commit_group;" ::: "memory");

    float acc[2][7][4];
#pragma unroll
    for (int mt = 0; mt < 2; mt++)
#pragma unroll
        for (int nt = 0; nt < 7; nt++)
#pragma unroll
            for (int q = 0; q < 4; q++) acc[mt][nt][q] = 0.0f;

    for (int c = 0; c < CH; c++) {
        int s = c % 3;
        asm volatile("cp.async.wait_group 1;" ::: "memory");
        __syncthreads();
        if (c + 2 < CH) issue(c + 2, (c + 2) % 3);
        asm volatile("cp.async.commit_group;" ::: "memory");

        const float* hp = hb + s * 128 + wm * 32;
        const float h0 = hp[g], h1 = hp[g + 8], h2 = hp[16 + g], h3 = hp[24 + g];
        const float* bp = bbuf + s * 4992 + (wn * 32 + lane) * 78;
        const float* xp = xs + wm * 32 + g;

#pragma unroll
        for (int ks = 0; ks < 5; ks++) {
            const int kk = ks * 8 + t4;
            const float* x0p = xp + kk * 136;
            const float* x1p = xp + (kk + 4) * 136;
            // A fragments: a0(row g,col kk) a1(row g+8,kk) a2(row g,kk+4) a3(row g+8,kk+4)
            uint32_t a00 = f2tf32(x0p[0]  * h0);
            uint32_t a01 = f2tf32(x0p[8]  * h1);
            uint32_t a02 = f2tf32(x1p[0]  * h0);
            uint32_t a03 = f2tf32(x1p[8]  * h1);
            uint32_t a10 = f2tf32(x0p[16] * h2);
            uint32_t a11 = f2tf32(x0p[24] * h3);
            uint32_t a12 = f2tf32(x1p[16] * h2);
            uint32_t a13 = f2tf32(x1p[24] * h3);
#pragma unroll
            for (int nt = 0; nt < 7; nt++) {
                float2 bv = *(const float2*)(bp + nt * 10 + ks * 2);
                uint32_t b0 = __float_as_uint(bv.x);
                uint32_t b1 = __float_as_uint(bv.y);
                mma8(acc[0][nt], a00, a01, a02, a03, b0, b1);
                mma8(acc[1][nt], a10, a11, a12, a13, b0, b1);
            }
        }
    }

    // store: c0:(row g, col 2t) c1:(g,2t+1) c2:(g+8,2t) c3:(g+8,2t+1)
#pragma unroll
    for (int mt = 0; mt < 2; mt++) {
        int r0 = m0 + wm * 32 + mt * 16 + g;
#pragma unroll
        for (int nt = 0; nt < 7; nt++) {
            int n0 = ns * 112 + wn * 56 + nt * 8 + t4 * 2;
            if (n0 < 200) {
                Hout[(size_t)n0 * MT + r0]           = acc[mt][nt][0];
                Hout[(size_t)(n0 + 1) * MT + r0]     = acc[mt][nt][1];
                Hout[(size_t)n0 * MT + r0 + 8]       = acc[mt][nt][2];
                Hout[(size_t)(n0 + 1) * MT + r0 + 8] = acc[mt][nt][3];
            }
        }
    }
}

// ---------------------------------------------------------------- reduction
__global__ void reduce_out_kernel(float* __restrict__ out) {
    int idx = blockIdx.x * blockDim.x + threadIdx.x;
    if (idx >= 512 * 600) return;
    int b = idx / 600, no = idx - b * 600;
    const float* H = (no < 200) ? g_Ht1 : (no < 400 ? g_Ht2 : g_Ht3);
    int n = no % 200;
    const float4* p = (const float4*)(H + (size_t)n * MT + b * 32);
    float s = 0.0f;
#pragma unroll
    for (int q = 0; q < 8; q++) {
        float4 v = p[q];
        s += v.x + v.y + v.z + v.w;
    }
    out[idx] = s;
}

// ---------------------------------------------------------------- launch
extern "C" void kernel_launch(void* const* d_in, const int* in_sizes, int n_in,
                              void* d_out, int out_size) {
    const float* inp = (const float*)d_in[0];
    const float* W0  = (const float*)d_in[1];
    const float* W1  = (const float*)d_in[2];
    const float* W2  = (const float*)d_in[3];
    float* out = (float*)d_out;

    void *pXt, *pH1, *pH2, *pH3, *pB0, *pB1, *pB2;
    cudaGetSymbolAddress(&pXt, g_Xt);
    cudaGetSymbolAddress(&pH1, g_Ht1);
    cudaGetSymbolAddress(&pH2, g_Ht2);
    cudaGetSymbolAddress(&pH3, g_Ht3);
    cudaGetSymbolAddress(&pB0, g_B0);
    cudaGetSymbolAddress(&pB1, g_B1);
    cudaGetSymbolAddress(&pB2, g_B2);
    float* Xt = (float*)pXt;
    float* H1 = (float*)pH1;
    float* H2 = (float*)pH2;
    float* H3 = (float*)pH3;
    float* B0 = (float*)pB0;
    float* B1 = (float*)pB1;
    float* B2 = (float*)pB2;

    const int SMEM = 59904 + 21760 + 1536;   // 83200 B
    cudaFuncSetAttribute(cin_mma_layer<40>,
                         cudaFuncAttributeMaxDynamicSharedMemorySize, SMEM);
    cudaFuncSetAttribute(cin_mma_layer<200>,
                         cudaFuncAttributeMaxDynamicSharedMemorySize, SMEM);

    transpose_x_kernel<<<(F0 * MT + 255) / 256, 256>>>(inp);

    prep_blob_kernel<<<(40  * BLOB_CH_FLOATS + 255) / 256, 256>>>(W0, B0, 40,  40);
    prep_blob_kernel<<<(200 * BLOB_CH_FLOATS + 255) / 256, 256>>>(W1, B1, 200, 200);
    prep_blob_kernel<<<(200 * BLOB_CH_FLOATS + 255) / 256, 256>>>(W2, B2, 200, 200);

    cin_mma_layer<40> <<<256, 256, SMEM>>>(Xt, B0, H1);
    cin_mma_layer<200><<<256, 256, SMEM>>>(H1, B1, H2);
    cin_mma_layer<200><<<256, 256, SMEM>>>(H2, B2, H3);

    reduce_out_kernel<<<(512 * 600 + 255) / 256, 256>>>(out);
}

// round 5
// speedup vs baseline: 7.9399x; 1.4758x over previous
#include <cuda_runtime.h>
#include <cuda_fp16.h>
#include <cstdint>

// ===========================================================================
// CIN (xDeepFM) on GB300 via mma.sync fp16 (f32 accum).
// Hnext[m,n] = sum_{i,j} X[m,i] Hprev[m,j] W[i*FI+j, n],  m = b*32+d, M=16384.
// Generated-A GEMM, K ordered (j outer, i inner): per 40-wide chunk (fixed j)
// A[m,i] = X[m,i]*Hprev[m,j] is built in registers from an x-tile ([m][40]
// smem layout, LDS.64 col-pairs) and one h column; products computed in fp32,
// rounded ONCE to fp16 (cvt.rn.f16x2). K=40 = m16n8k16 + m16n8k16 + m16n8k8.
// W pre-packed to per-lane fragment half2 words (stride 38 -> conflict-free),
// streamed with cp.async 3-stage pipeline.
// ===========================================================================

constexpr int MT  = 16384;
constexpr int NSZ = 200;
constexpr int F0  = 40;

constexpr int LW       = 38;                  // words per lane per (chunk,ns)
constexpr int BNS      = 2 * 32 * LW * 4;     // bytes per (chunk, ns) = 9728
constexpr int BLOB_CHW = 2 * 2 * 32 * LW;     // words per chunk = 4864

__device__ float g_Xt [F0  * MT];
__device__ float g_Ht1[NSZ * MT];
__device__ float g_Ht2[NSZ * MT];
__device__ float g_Ht3[NSZ * MT];
__device__ __align__(16) uint32_t g_B0[40  * BLOB_CHW];
__device__ __align__(16) uint32_t g_B1[200 * BLOB_CHW];
__device__ __align__(16) uint32_t g_B2[200 * BLOB_CHW];

// ---------------------------------------------------------------- helpers
__device__ __forceinline__ uint32_t smem_u32(const void* p) {
    uint32_t a;
    asm("{ .reg .u64 t; cvta.to.shared.u64 t, %1; cvt.u32.u64 %0, t; }"
        : "=r"(a) : "l"(p));
    return a;
}

// pack two f32 -> f16x2, lo in lower half (PTX: first src = upper half)
__device__ __forceinline__ uint32_t pack_h2(float lo, float hi) {
    uint32_t u;
    asm("cvt.rn.f16x2.f32 %0, %1, %2;" : "=r"(u) : "f"(hi), "f"(lo));
    return u;
}

__device__ __forceinline__ void cp16(uint32_t dst_smem, const void* src) {
    asm volatile("cp.async.cg.shared.global [%0], [%1], 16;"
                 :: "r"(dst_smem), "l"(src) : "memory");
}

__device__ __forceinline__ void mma16(float* d,
                                      uint32_t a0, uint32_t a1, uint32_t a2, uint32_t a3,
                                      uint32_t b0, uint32_t b1) {
    asm volatile(
        "mma.sync.aligned.m16n8k16.row.col.f32.f16.f16.f32 "
        "{%0,%1,%2,%3}, {%4,%5,%6,%7}, {%8,%9}, {%0,%1,%2,%3};"
        : "+f"(d[0]), "+f"(d[1]), "+f"(d[2]), "+f"(d[3])
        : "r"(a0), "r"(a1), "r"(a2), "r"(a3), "r"(b0), "r"(b1));
}

__device__ __forceinline__ void mma8(float* d,
                                     uint32_t a0, uint32_t a1, uint32_t b0) {
    asm volatile(
        "mma.sync.aligned.m16n8k8.row.col.f32.f16.f16.f32 "
        "{%0,%1,%2,%3}, {%4,%5}, {%6}, {%0,%1,%2,%3};"
        : "+f"(d[0]), "+f"(d[1]), "+f"(d[2]), "+f"(d[3])
        : "r"(a0), "r"(a1), "r"(b0));
}

// ---------------------------------------------------------------- prep
// Xt[i][m] = inputs[b, i, d], m = b*32+d
__global__ void transpose_x_kernel(const float* __restrict__ inp) {
    int idx = blockIdx.x * blockDim.x + threadIdx.x;
    if (idx >= F0 * MT) return;
    int i = idx >> 14;
    int m = idx & (MT - 1);
    int b = m >> 5, d = m & 31;
    g_Xt[idx] = inp[b * (F0 * 32) + i * 32 + d];
}

// blob[j][ns][nw][lane][v], v<38:
//   v<28 : q=v/14, r=v%14, nt=r>>1, w=r&1, u=2q+w
//   28<=v<35 : nt=v-28, u=4
//   v>=35: pad 0
//   n = ns*112 + nw*56 + nt*8 + (lane>>2)
//   i0 = u*8 + (lane&3)*2 ; word = h2(W[i0], W[i0+1]) rows (i*FI+j), col n
__global__ void prep_blob_kernel(const float* __restrict__ W,
                                 uint32_t* __restrict__ blob, int FI, int CH) {
    int idx = blockIdx.x * blockDim.x + threadIdx.x;
    if (idx >= CH * BLOB_CHW) return;
    int v = idx % LW;
    int t = idx / LW;
    int lane = t & 31; t >>= 5;
    int nw   = t & 1;  t >>= 1;
    int ns   = t & 1;
    int j    = t >> 1;

    uint32_t word = 0;
    if (v < 35) {
        int nt, u;
        if (v < 28) { int q = v / 14, r = v - q * 14; nt = r >> 1; u = 2 * q + (r & 1); }
        else        { nt = v - 28; u = 4; }
        int n  = ns * 112 + nw * 56 + nt * 8 + (lane >> 2);
        int i0 = u * 8 + (lane & 3) * 2;
        if (n < 200) {
            float lo = W[((size_t)i0 * FI + j) * 200 + n];
            float hi = W[((size_t)(i0 + 1) * FI + j) * 200 + n];
            word = pack_h2(lo, hi);
        }
    }
    blob[idx] = word;
}

// ---------------------------------------------------------------- layer
// grid 256: (bx>>1)=m-block(128 rows), (bx&1)=ns (112 n). 8 warps: wm=wid&3, wn=wid>>2.
// smem: bbuf 3*9728 | xs[m][40] 20480 | hb 3*128*4  = 51200 B
template <int CH>
__global__ __launch_bounds__(256, 2)
void cin_fp16_layer(const float* __restrict__ Hprev,    // [CH][MT]
                    const uint32_t* __restrict__ blob,
                    float* __restrict__ Hout)           // [200][MT]
{
    extern __shared__ __align__(16) char smem[];
    uint32_t* bbuf = (uint32_t*)smem;                   // 3 * 2432 words
    float*    xs   = (float*)(smem + 3 * BNS);          // 128 * 40
    float*    hb   = (float*)(smem + 3 * BNS + 20480);  // 3 * 128

    const int tid  = threadIdx.x;
    const int lane = tid & 31;
    const int wid  = tid >> 5;
    const int wm   = wid & 3;
    const int wn   = wid >> 2;
    const int g    = lane >> 2;
    const int t4   = lane & 3;
    const int m0   = (blockIdx.x >> 1) * 128;
    const int ns   = blockIdx.x & 1;

    // x tile: xs[m*40 + i]  (gmem reads coalesced over m per i-row)
    for (int idx = tid; idx < 40 * 128; idx += 256) {
        int i = idx >> 7, m = idx & 127;
        xs[m * 40 + i] = g_Xt[i * MT + m0 + m];
    }

    const uint32_t uB = smem_u32(bbuf);
    const uint32_t uH = smem_u32(hb);

    auto issue = [&](int c, int s) {
        const char* srcB = (const char*)(blob + ((size_t)c * 2 + ns) * (2 * 32 * LW));
        uint32_t dB = uB + s * BNS;
        for (int t = tid * 16; t < BNS; t += 256 * 16)
            cp16(dB + t, srcB + t);
        if (tid < 32)
            cp16(uH + s * 512 + tid * 16,
                 (const char*)(Hprev + (size_t)c * MT + m0) + tid * 16);
    };

    issue(0, 0);
    asm volatile("cp.async.commit_group;" ::: "memory");
    issue(1, 1);
    asm volatile("cp.async.commit_group;" ::: "memory");

    float acc[2][7][4];
#pragma unroll
    for (int mt = 0; mt < 2; mt++)
#pragma unroll
        for (int nt = 0; nt < 7; nt++)
#pragma unroll
            for (int q = 0; q < 4; q++) acc[mt][nt][q] = 0.0f;

    const float* xp = xs + (wm * 32 + g) * 40;

    for (int c = 0; c < CH; c++) {
        int s = c % 3;
        asm volatile("cp.async.wait_group 1;" ::: "memory");
        __syncthreads();
        if (c + 2 < CH) issue(c + 2, (c + 2) % 3);
        asm volatile("cp.async.commit_group;" ::: "memory");

        const float* hp = hb + s * 128 + wm * 32;
        const float h0 = hp[g], h1 = hp[g + 8], h2v = hp[g + 16], h3 = hp[g + 24];

        // A fragments: rows rs0..3 = g, g+8, g+16, g+24 ; col-pairs p: i = p*8 + 2*t4
        uint32_t a[4][5];
#pragma unroll
        for (int p = 0; p < 5; p++) {
            const int ib = p * 8 + 2 * t4;
            float2 x0 = *(const float2*)(xp + ib);                //  row g
            float2 x1 = *(const float2*)(xp + 8 * 40 + ib);       //  row g+8
            float2 x2 = *(const float2*)(xp + 16 * 40 + ib);      //  row g+16
            float2 x3 = *(const float2*)(xp + 24 * 40 + ib);      //  row g+24
            a[0][p] = pack_h2(x0.x * h0,  x0.y * h0);
            a[1][p] = pack_h2(x1.x * h1,  x1.y * h1);
            a[2][p] = pack_h2(x2.x * h2v, x2.y * h2v);
            a[3][p] = pack_h2(x3.x * h3,  x3.y * h3);
        }

        const uint32_t* bp = bbuf + s * (2 * 32 * LW) + (wn * 32 + lane) * LW;
#pragma unroll
        for (int nt = 0; nt < 7; nt++) {
            uint2 q0 = *(const uint2*)(bp + nt * 2);          // u0,u1 (k 0..15)
            uint2 q1 = *(const uint2*)(bp + 14 + nt * 2);     // u2,u3 (k 16..31)
            uint32_t b4 = bp[28 + nt];                        // u4    (k 32..39)
            mma16(acc[0][nt], a[0][0], a[1][0], a[0][1], a[1][1], q0.x, q0.y);
            mma16(acc[0][nt], a[0][2], a[1][2], a[0][3], a[1][3], q1.x, q1.y);
            mma8 (acc[0][nt], a[0][4], a[1][4], b4);
            mma16(acc[1][nt], a[2][0], a[3][0], a[2][1], a[3][1], q0.x, q0.y);
            mma16(acc[1][nt], a[2][2], a[3][2], a[2][3], a[3][3], q1.x, q1.y);
            mma8 (acc[1][nt], a[2][4], a[3][4], b4);
        }
    }

    // store (Hout transposed [n][m])
#pragma unroll
    for (int mt = 0; mt < 2; mt++) {
        int r0 = m0 + wm * 32 + mt * 16 + g;
#pragma unroll
        for (int nt = 0; nt < 7; nt++) {
            int n0 = ns * 112 + wn * 56 + nt * 8 + t4 * 2;
            if (n0 < 200) {
                Hout[(size_t)n0 * MT + r0]           = acc[mt][nt][0];
                Hout[(size_t)(n0 + 1) * MT + r0]     = acc[mt][nt][1];
                Hout[(size_t)n0 * MT + r0 + 8]       = acc[mt][nt][2];
                Hout[(size_t)(n0 + 1) * MT + r0 + 8] = acc[mt][nt][3];
            }
        }
    }
}

// ---------------------------------------------------------------- reduction
__global__ void reduce_out_kernel(float* __restrict__ out) {
    int idx = blockIdx.x * blockDim.x + threadIdx.x;
    if (idx >= 512 * 600) return;
    int b = idx / 600, no = idx - b * 600;
    const float* H = (no < 200) ? g_Ht1 : (no < 400 ? g_Ht2 : g_Ht3);
    int n = no % 200;
    const float4* p = (const float4*)(H + (size_t)n * MT + b * 32);
    float s = 0.0f;
#pragma unroll
    for (int q = 0; q < 8; q++) {
        float4 v = p[q];
        s += v.x + v.y + v.z + v.w;
    }
    out[idx] = s;
}

// ---------------------------------------------------------------- launch
extern "C" void kernel_launch(void* const* d_in, const int* in_sizes, int n_in,
                              void* d_out, int out_size) {
    const float* inp = (const float*)d_in[0];
    const float* W0  = (const float*)d_in[1];
    const float* W1  = (const float*)d_in[2];
    const float* W2  = (const float*)d_in[3];
    float* out = (float*)d_out;

    void *pXt, *pH1, *pH2, *pH3, *pB0, *pB1, *pB2;
    cudaGetSymbolAddress(&pXt, g_Xt);
    cudaGetSymbolAddress(&pH1, g_Ht1);
    cudaGetSymbolAddress(&pH2, g_Ht2);
    cudaGetSymbolAddress(&pH3, g_Ht3);
    cudaGetSymbolAddress(&pB0, g_B0);
    cudaGetSymbolAddress(&pB1, g_B1);
    cudaGetSymbolAddress(&pB2, g_B2);
    float*    Xt = (float*)pXt;
    float*    H1 = (float*)pH1;
    float*    H2 = (float*)pH2;
    float*    H3 = (float*)pH3;
    uint32_t* B0 = (uint32_t*)pB0;
    uint32_t* B1 = (uint32_t*)pB1;
    uint32_t* B2 = (uint32_t*)pB2;

    const int SMEM = 3 * BNS + 20480 + 1536;   // 51200 B
    cudaFuncSetAttribute(cin_fp16_layer<40>,
                         cudaFuncAttributeMaxDynamicSharedMemorySize, SMEM);
    cudaFuncSetAttribute(cin_fp16_layer<200>,
                         cudaFuncAttributeMaxDynamicSharedMemorySize, SMEM);

    transpose_x_kernel<<<(F0 * MT + 255) / 256, 256>>>(inp);

    prep_blob_kernel<<<(40  * BLOB_CHW + 255) / 256, 256>>>(W0, B0, 40,  40);
    prep_blob_kernel<<<(200 * BLOB_CHW + 255) / 256, 256>>>(W1, B1, 200, 200);
    prep_blob_kernel<<<(200 * BLOB_CHW + 255) / 256, 256>>>(W2, B2, 200, 200);

    cin_fp16_layer<40> <<<256, 256, SMEM>>>(Xt, B0, H1);
    cin_fp16_layer<200><<<256, 256, SMEM>>>(H1, B1, H2);
    cin_fp16_layer<200><<<256, 256, SMEM>>>(H2, B2, H3);

    reduce_out_kernel<<<(512 * 600 + 255) / 256, 256>>>(out);
}

// round 6
// speedup vs baseline: 9.1466x; 1.1520x over previous
#include <cuda_runtime.h>
#include <cuda_fp16.h>
#include <cstdint>

// ===========================================================================
// CIN (xDeepFM) on GB300 via mma.sync fp16 (f32 accum), chunk-paired K=80.
// Hnext[m,n] = sum_{i,j} X[m,i] Hprev[m,j] W[i*FI+j, n],  m = b*32+d, M=16384.
// Generated-A GEMM, K = (j outer, i inner). Chunks (fixed j, 40 k) processed
// in PAIRS: K=80 = 5 x m16n8k16 (no k8 mma). Exact N tiling: 25 n-tiles of 8
// split (7,6,6,6) across (ns,wn) — zero N padding.
// Products computed fp32, rounded once to fp16. W pre-packed per-lane
// fragment words (stride 38), cp.async 3-stage (per-pair) pipeline.
// ===========================================================================

constexpr int MT  = 16384;
constexpr int F0  = 40;

constexpr int LW        = 38;                 // words per lane per (chunk,ns)
constexpr int CB_WORDS  = 2 * 32 * LW;        // words per (chunk,ns) block = 2432
constexpr int BLOB_CHW  = 2 * CB_WORDS;       // words per chunk (both ns) = 4864
constexpr int PAIR_B    = 2 * CB_WORDS * 4;   // bytes per pair per ns = 19456

__device__ float g_Xt [F0  * MT];
__device__ float g_Ht1[200 * MT];
__device__ float g_Ht2[200 * MT];
__device__ float g_Ht3[200 * MT];
__device__ __align__(16) uint32_t g_B0[40  * BLOB_CHW];
__device__ __align__(16) uint32_t g_B1[200 * BLOB_CHW];
__device__ __align__(16) uint32_t g_B2[200 * BLOB_CHW];

// ---------------------------------------------------------------- helpers
__device__ __forceinline__ uint32_t smem_u32(const void* p) {
    uint32_t a;
    asm("{ .reg .u64 t; cvta.to.shared.u64 t, %1; cvt.u32.u64 %0, t; }"
        : "=r"(a) : "l"(p));
    return a;
}

__device__ __forceinline__ uint32_t pack_h2(float lo, float hi) {
    uint32_t u;
    asm("cvt.rn.f16x2.f32 %0, %1, %2;" : "=r"(u) : "f"(hi), "f"(lo));
    return u;
}

__device__ __forceinline__ void cp16(uint32_t dst_smem, const void* src) {
    asm volatile("cp.async.cg.shared.global [%0], [%1], 16;"
                 :: "r"(dst_smem), "l"(src) : "memory");
}

__device__ __forceinline__ void mma16(float* d,
                                      uint32_t a0, uint32_t a1, uint32_t a2, uint32_t a3,
                                      uint32_t b0, uint32_t b1) {
    asm volatile(
        "mma.sync.aligned.m16n8k16.row.col.f32.f16.f16.f32 "
        "{%0,%1,%2,%3}, {%4,%5,%6,%7}, {%8,%9}, {%0,%1,%2,%3};"
        : "+f"(d[0]), "+f"(d[1]), "+f"(d[2]), "+f"(d[3])
        : "r"(a0), "r"(a1), "r"(a2), "r"(a3), "r"(b0), "r"(b1));
}

// ---------------------------------------------------------------- prep
__global__ void transpose_x_kernel(const float* __restrict__ inp) {
    int idx = blockIdx.x * blockDim.x + threadIdx.x;
    if (idx >= F0 * MT) return;
    int i = idx >> 14;
    int m = idx & (MT - 1);
    int b = m >> 5, d = m & 31;
    g_Xt[idx] = inp[b * (F0 * 32) + i * 32 + d];
}

// blob layout: [ns][j][nw][lane][v]  (v < 38)
//   v<28 : q=v/14, r=v%14, nt=r>>1, u=2q+(r&1);  28<=v<35: nt=v-28, u=4
//   n  = ns*104 + nw*(ns?48:56) + nt*8 + (lane>>2)
//   i0 = u*8 + (lane&3)*2 ; word = h2(W[(i0*FI+j)*200+n], W[((i0+1)*FI+j)*200+n])
//   valid iff nt < ((ns||nw) ? 6 : 7), else 0
__global__ void prep_blob_kernel(const float* __restrict__ W,
                                 uint32_t* __restrict__ blob, int FI, int CH) {
    int idx = blockIdx.x * blockDim.x + threadIdx.x;
    if (idx >= CH * BLOB_CHW) return;
    int v = idx % LW;
    int t = idx / LW;
    int lane = t & 31; t >>= 5;
    int nw   = t & 1;  t >>= 1;
    int j    = t % CH;
    int ns   = t / CH;

    uint32_t word = 0;
    int ntc = (ns == 0 && nw == 0) ? 7 : 6;
    if (v < 35) {
        int nt, u;
        if (v < 28) { int q = v / 14, r = v - q * 14; nt = r >> 1; u = 2 * q + (r & 1); }
        else        { nt = v - 28; u = 4; }
        if (nt < ntc) {
            int n  = ns * 104 + nw * (ns ? 48 : 56) + nt * 8 + (lane >> 2);
            int i0 = u * 8 + (lane & 3) * 2;
            float lo = W[((size_t)i0 * FI + j) * 200 + n];
            float hi = W[((size_t)(i0 + 1) * FI + j) * 200 + n];
            word = pack_h2(lo, hi);
        }
    }
    blob[idx] = word;
}

// ---------------------------------------------------------------- layer
// grid 256: (bx>>1)=m-block(128), (bx&1)=ns. 8 warps: wm=wid&3 (32 m), wn=wid>>2.
// n tiles: (ns,wn)=(0,0):7 else 6;  n_base = ns*104 + wn*(ns?48:56).
// smem: bbuf 3*19456 | xs[m][40] 20480 | hb[3][2][128] 3072  = 81920 B
template <int CH>
__global__ __launch_bounds__(256, 2)
void cin_fp16_layer(const float* __restrict__ Hprev,    // [CH][MT]
                    const uint32_t* __restrict__ blob,  // [ns][CH][2432]
                    float* __restrict__ Hout)           // [200][MT]
{
    constexpr int CHP = CH / 2;
    extern __shared__ __align__(16) char smem[];
    uint32_t* bbuf = (uint32_t*)smem;                     // 3 * 4864 words
    float*    xs   = (float*)(smem + 3 * PAIR_B);         // 128 * 40
    float*    hb   = (float*)(smem + 3 * PAIR_B + 20480); // 3 * 2 * 128

    const int tid  = threadIdx.x;
    const int lane = tid & 31;
    const int wid  = tid >> 5;
    const int wm   = wid & 3;
    const int wn   = wid >> 2;
    const int g    = lane >> 2;
    const int t4   = lane & 3;
    const int m0   = (blockIdx.x >> 1) * 128;
    const int ns   = blockIdx.x & 1;
    const int ntc  = (ns == 0 && wn == 0) ? 7 : 6;
    const int nb   = ns * 104 + wn * (ns ? 48 : 56);

    for (int idx = tid; idx < 40 * 128; idx += 256) {
        int i = idx >> 7, m = idx & 127;
        xs[m * 40 + i] = g_Xt[i * MT + m0 + m];
    }

    const uint32_t uB = smem_u32(bbuf);
    const uint32_t uH = smem_u32(hb);
    const char* blob_ns = (const char*)(blob + (size_t)ns * CH * CB_WORDS);

    auto issue = [&](int p, int s) {
        const char* srcB = blob_ns + (size_t)(2 * p) * (CB_WORDS * 4);
        uint32_t dB = uB + s * PAIR_B;
        for (int t = tid * 16; t < PAIR_B; t += 256 * 16)
            cp16(dB + t, srcB + t);
        if (tid < 64) {
            int cc = tid >> 5;
            cp16(uH + s * 1024 + cc * 512 + (tid & 31) * 16,
                 (const char*)(Hprev + (size_t)(2 * p + cc) * MT + m0) + (tid & 31) * 16);
        }
    };

    issue(0, 0);
    asm volatile("cp.async.commit_group;" ::: "memory");
    issue(1, 1);
    asm volatile("cp.async.commit_group;" ::: "memory");

    float acc[2][7][4];
#pragma unroll
    for (int mt = 0; mt < 2; mt++)
#pragma unroll
        for (int nt = 0; nt < 7; nt++)
#pragma unroll
            for (int q = 0; q < 4; q++) acc[mt][nt][q] = 0.0f;

    const float* xp = xs + (wm * 32 + g) * 40;

    for (int p = 0; p < CHP; p++) {
        int s = p % 3;
        asm volatile("cp.async.wait_group 1;" ::: "memory");
        __syncthreads();
        if (p + 2 < CHP) issue(p + 2, (p + 2) % 3);
        asm volatile("cp.async.commit_group;" ::: "memory");

        const float* hc = hb + s * 256 + wm * 32;          // chunk 2p
        const float* hd = hc + 128;                        // chunk 2p+1
        float hc0 = hc[g], hc1 = hc[g + 8], hc2 = hc[g + 16], hc3 = hc[g + 24];
        float hd0 = hd[g], hd1 = hd[g + 8], hd2 = hd[g + 16], hd3 = hd[g + 24];

        uint32_t a[4][5], b[4][5];
#pragma unroll
        for (int pb = 0; pb < 5; pb++) {
            const int ib = pb * 8 + 2 * t4;
            float2 x0 = *(const float2*)(xp + ib);
            float2 x1 = *(const float2*)(xp + 8 * 40 + ib);
            float2 x2 = *(const float2*)(xp + 16 * 40 + ib);
            float2 x3 = *(const float2*)(xp + 24 * 40 + ib);
            a[0][pb] = pack_h2(x0.x * hc0, x0.y * hc0);
            a[1][pb] = pack_h2(x1.x * hc1, x1.y * hc1);
            a[2][pb] = pack_h2(x2.x * hc2, x2.y * hc2);
            a[3][pb] = pack_h2(x3.x * hc3, x3.y * hc3);
            b[0][pb] = pack_h2(x0.x * hd0, x0.y * hd0);
            b[1][pb] = pack_h2(x1.x * hd1, x1.y * hd1);
            b[2][pb] = pack_h2(x2.x * hd2, x2.y * hd2);
            b[3][pb] = pack_h2(x3.x * hd3, x3.y * hd3);
        }

        const uint32_t* bpc = bbuf + s * (2 * CB_WORDS) + (wn * 32 + lane) * LW;
        const uint32_t* bpd = bpc + CB_WORDS;
#pragma unroll
        for (int nt = 0; nt < 7; nt++) {
            if (nt < ntc) {
                uint2 u01 = *(const uint2*)(bpc + nt * 2);
                uint2 u23 = *(const uint2*)(bpc + 14 + nt * 2);
                uint32_t u4 = bpc[28 + nt];
                uint2 v01 = *(const uint2*)(bpd + nt * 2);
                uint2 v23 = *(const uint2*)(bpd + 14 + nt * 2);
                uint32_t v4 = bpd[28 + nt];
                mma16(acc[0][nt], a[0][0], a[1][0], a[0][1], a[1][1], u01.x, u01.y);
                mma16(acc[0][nt], a[0][2], a[1][2], a[0][3], a[1][3], u23.x, u23.y);
                mma16(acc[0][nt], a[0][4], a[1][4], b[0][0], b[1][0], u4,    v01.x);
                mma16(acc[0][nt], b[0][1], b[1][1], b[0][2], b[1][2], v01.y, v23.x);
                mma16(acc[0][nt], b[0][3], b[1][3], b[0][4], b[1][4], v23.y, v4);
                mma16(acc[1][nt], a[2][0], a[3][0], a[2][1], a[3][1], u01.x, u01.y);
                mma16(acc[1][nt], a[2][2], a[3][2], a[2][3], a[3][3], u23.x, u23.y);
                mma16(acc[1][nt], a[2][4], a[3][4], b[2][0], b[3][0], u4,    v01.x);
                mma16(acc[1][nt], b[2][1], b[3][1], b[2][2], b[3][2], v01.y, v23.x);
                mma16(acc[1][nt], b[2][3], b[3][3], b[2][4], b[3][4], v23.y, v4);
            }
        }
    }

    // store (Hout transposed [n][m])
#pragma unroll
    for (int mt = 0; mt < 2; mt++) {
        int r0 = m0 + wm * 32 + mt * 16 + g;
#pragma unroll
        for (int nt = 0; nt < 7; nt++) {
            if (nt < ntc) {
                int n0 = nb + nt * 8 + t4 * 2;
                Hout[(size_t)n0 * MT + r0]           = acc[mt][nt][0];
                Hout[(size_t)(n0 + 1) * MT + r0]     = acc[mt][nt][1];
                Hout[(size_t)n0 * MT + r0 + 8]       = acc[mt][nt][2];
                Hout[(size_t)(n0 + 1) * MT + r0 + 8] = acc[mt][nt][3];
            }
        }
    }
}

// ---------------------------------------------------------------- reduction
__global__ void reduce_out_kernel(float* __restrict__ out) {
    int idx = blockIdx.x * blockDim.x + threadIdx.x;
    if (idx >= 512 * 600) return;
    int b = idx / 600, no = idx - b * 600;
    const float* H = (no < 200) ? g_Ht1 : (no < 400 ? g_Ht2 : g_Ht3);
    int n = no % 200;
    const float4* p = (const float4*)(H + (size_t)n * MT + b * 32);
    float s = 0.0f;
#pragma unroll
    for (int q = 0; q < 8; q++) {
        float4 v = p[q];
        s += v.x + v.y + v.z + v.w;
    }
    out[idx] = s;
}

// ---------------------------------------------------------------- launch
extern "C" void kernel_launch(void* const* d_in, const int* in_sizes, int n_in,
                              void* d_out, int out_size) {
    const float* inp = (const float*)d_in[0];
    const float* W0  = (const float*)d_in[1];
    const float* W1  = (const float*)d_in[2];
    const float* W2  = (const float*)d_in[3];
    float* out = (float*)d_out;

    void *pXt, *pH1, *pH2, *pH3, *pB0, *pB1, *pB2;
    cudaGetSymbolAddress(&pXt, g_Xt);
    cudaGetSymbolAddress(&pH1, g_Ht1);
    cudaGetSymbolAddress(&pH2, g_Ht2);
    cudaGetSymbolAddress(&pH3, g_Ht3);
    cudaGetSymbolAddress(&pB0, g_B0);
    cudaGetSymbolAddress(&pB1, g_B1);
    cudaGetSymbolAddress(&pB2, g_B2);
    float*    Xt = (float*)pXt;
    float*    H1 = (float*)pH1;
    float*    H2 = (float*)pH2;
    float*    H3 = (float*)pH3;
    uint32_t* B0 = (uint32_t*)pB0;
    uint32_t* B1 = (uint32_t*)pB1;
    uint32_t* B2 = (uint32_t*)pB2;

    const int SMEM = 3 * PAIR_B + 20480 + 3072;   // 81920 B
    cudaFuncSetAttribute(cin_fp16_layer<40>,
                         cudaFuncAttributeMaxDynamicSharedMemorySize, SMEM);
    cudaFuncSetAttribute(cin_fp16_layer<200>,
                         cudaFuncAttributeMaxDynamicSharedMemorySize, SMEM);

    transpose_x_kernel<<<(F0 * MT + 255) / 256, 256>>>(inp);

    prep_blob_kernel<<<(40  * BLOB_CHW + 255) / 256, 256>>>(W0, B0, 40,  40);
    prep_blob_kernel<<<(200 * BLOB_CHW + 255) / 256, 256>>>(W1, B1, 200, 200);
    prep_blob_kernel<<<(200 * BLOB_CHW + 255) / 256, 256>>>(W2, B2, 200, 200);

    cin_fp16_layer<40> <<<256, 256, SMEM>>>(Xt, B0, H1);
    cin_fp16_layer<200><<<256, 256, SMEM>>>(H1, B1, H2);
    cin_fp16_layer<200><<<256, 256, SMEM>>>(H2, B2, H3);

    reduce_out_kernel<<<(512 * 600 + 255) / 256, 256>>>(out);
}

// round 7
// speedup vs baseline: 9.9755x; 1.0906x over previous
#include <cuda_runtime.h>
#include <cuda_fp16.h>
#include <cstdint>

// ===========================================================================
// CIN (xDeepFM) on GB300 via mma.sync fp16 (f32 accum).
// Hnext[m,n] = sum_{i,j} X[m,i] Hprev[m,j] W[i*FI+j, n],  m = b*32+d, M=16384.
// Generated-A GEMM, chunk-paired K=80 = 5 x m16n8k16.
// Scheduling: grid 147 CTAs (1/SM, single wave), BM=112 (7 m16 tiles),
// 512 threads / 16 warps. Warps get table-assigned (m16-tile, nt-range)
// loads {13,12,9,8} arranged for per-SMSP balance (max 45 vs avg 43.75).
// B blob pre-packed per K-pair as [nt][lane][12 words] (3 x LDS.128).
// ===========================================================================

constexpr int MT  = 16384;
constexpr int F0  = 40;
constexpr int BM  = 112;
constexpr int NT  = 25;

constexpr int STG_BW   = NT * 32 * 12;        // B words per pair-stage = 9600
constexpr int STG_BB   = STG_BW * 4;          // 38400 B
constexpr int GRID     = 147;                 // ceil(16384/112)

__device__ float g_Xt [F0  * MT + 256];
__device__ float g_Ht1[200 * MT + 256];
__device__ float g_Ht2[200 * MT + 256];
__device__ float g_Ht3[200 * MT + 256];
__device__ __align__(16) uint32_t g_B0[20  * STG_BW];   // small layer: 20 pairs
__device__ __align__(16) uint32_t g_B1[100 * STG_BW];   // big: 100 pairs
__device__ __align__(16) uint32_t g_B2[100 * STG_BW];

// warp assignment: (m16 tile, nt0, cnt); SMSP sums (wid%4): 45,45,43,42
__constant__ int c_tile[16] = {2,3,4,5, 2,3,6,4, 5,6,0,1, 0,0,1,1};
__constant__ int c_nt0 [16] = {0,0,0,0, 13,13,0,13, 13,13,0,0, 9,17,9,17};
__constant__ int c_cnt [16] = {13,13,13,13, 12,12,13,12, 12,12,9,9, 8,8,8,8};

// ---------------------------------------------------------------- helpers
__device__ __forceinline__ uint32_t smem_u32(const void* p) {
    uint32_t a;
    asm("{ .reg .u64 t; cvta.to.shared.u64 t, %1; cvt.u32.u64 %0, t; }"
        : "=r"(a) : "l"(p));
    return a;
}

__device__ __forceinline__ uint32_t pack_h2(float lo, float hi) {
    uint32_t u;
    asm("cvt.rn.f16x2.f32 %0, %1, %2;" : "=r"(u) : "f"(hi), "f"(lo));
    return u;
}

__device__ __forceinline__ void cp16(uint32_t dst_smem, const void* src) {
    asm volatile("cp.async.cg.shared.global [%0], [%1], 16;"
                 :: "r"(dst_smem), "l"(src) : "memory");
}

__device__ __forceinline__ void mma16(float* d,
                                      uint32_t a0, uint32_t a1, uint32_t a2, uint32_t a3,
                                      uint32_t b0, uint32_t b1) {
    asm volatile(
        "mma.sync.aligned.m16n8k16.row.col.f32.f16.f16.f32 "
        "{%0,%1,%2,%3}, {%4,%5,%6,%7}, {%8,%9}, {%0,%1,%2,%3};"
        : "+f"(d[0]), "+f"(d[1]), "+f"(d[2]), "+f"(d[3])
        : "r"(a0), "r"(a1), "r"(a2), "r"(a3), "r"(b0), "r"(b1));
}

// ---------------------------------------------------------------- prep
__global__ void transpose_x_kernel(const float* __restrict__ inp) {
    int idx = blockIdx.x * blockDim.x + threadIdx.x;
    if (idx >= F0 * MT) return;
    int i = idx >> 14;
    int m = idx & (MT - 1);
    int b = m >> 5, d = m & 31;
    g_Xt[idx] = inp[b * (F0 * 32) + i * 32 + d];
}

// blob[p][nt][lane][v]:  v<5: u=v, j=2p;  5<=v<10: u=v-5, j=2p+1;  else 0.
//   n = nt*8 + (lane>>2);  i0 = u*8 + (lane&3)*2
//   word = h2( W[(i0*FI+j)*200+n], W[((i0+1)*FI+j)*200+n] )
__global__ void prep_blob_kernel(const float* __restrict__ W,
                                 uint32_t* __restrict__ blob, int FI, int NP) {
    int idx = blockIdx.x * blockDim.x + threadIdx.x;
    if (idx >= NP * STG_BW) return;
    int v = idx % 12;
    int t = idx / 12;
    int lane = t & 31; t >>= 5;
    int nt   = t % NT;
    int p    = t / NT;

    uint32_t word = 0;
    if (v < 10) {
        int u = (v < 5) ? v : v - 5;
        int j = 2 * p + (v >= 5);
        int n  = nt * 8 + (lane >> 2);
        int i0 = u * 8 + (lane & 3) * 2;
        float lo = W[((size_t)i0 * FI + j) * 200 + n];
        float hi = W[((size_t)(i0 + 1) * FI + j) * 200 + n];
        word = pack_h2(lo, hi);
    }
    blob[idx] = word;
}

// ---------------------------------------------------------------- layer
// smem: bstg 3*38400 | xs[BM][40] 17920 | hstg[3][2][BM] 2688  = 135808 B
template <int CH>
__global__ __launch_bounds__(512, 1)
void cin_fp16_layer(const float* __restrict__ Hprev,    // [CH][MT]
                    const uint32_t* __restrict__ blob,  // [CHP][STG_BW]
                    float* __restrict__ Hout)           // [200][MT]
{
    constexpr int CHP = CH / 2;
    extern __shared__ __align__(16) char smem[];
    uint32_t* bstg = (uint32_t*)smem;                        // 3 * 9600 words
    float*    xs   = (float*)(smem + 3 * STG_BB);            // BM * 40
    float*    hstg = (float*)(smem + 3 * STG_BB + 17920);    // 3 * 2 * BM

    const int tid  = threadIdx.x;
    const int lane = tid & 31;
    const int wid  = tid >> 5;
    const int g    = lane >> 2;
    const int t4   = lane & 3;
    const int m0   = blockIdx.x * BM;

    const int tile = c_tile[wid];
    const int nt0  = c_nt0[wid];
    const int cnt  = c_cnt[wid];
    const int row0 = tile * 16 + g;       // local row (g); row0+8 is the pair

    // x tile (clamp rows for last CTA)
    for (int idx = tid; idx < BM * 40; idx += 512) {
        int ml = idx / 40, i = idx - ml * 40;
        int gr = m0 + ml; if (gr > MT - 1) gr = MT - 1;
        xs[ml * 40 + i] = g_Xt[i * MT + gr];
    }

    const uint32_t uB = smem_u32(bstg);
    const uint32_t uH = smem_u32(hstg);

    auto issue = [&](int p, int s) {
        const char* srcB = (const char*)(blob + (size_t)p * STG_BW);
        uint32_t dB = uB + s * STG_BB;
        for (int t = tid * 16; t < STG_BB; t += 512 * 16)
            cp16(dB + t, srcB + t);
        if (tid < 56) {   // h: 2 chunks * 448 B
            int cc = tid / 28, q = tid - cc * 28;
            cp16(uH + s * (2 * BM * 4) + cc * (BM * 4) + q * 16,
                 (const char*)(Hprev + (size_t)(2 * p + cc) * MT + m0) + q * 16);
        }
    };

    issue(0, 0);
    asm volatile("cp.async.commit_group;" ::: "memory");
    issue(1, 1);
    asm volatile("cp.async.commit_group;" ::: "memory");

    float acc[13][4];
#pragma unroll
    for (int q = 0; q < 13; q++)
#pragma unroll
        for (int c = 0; c < 4; c++) acc[q][c] = 0.0f;

    for (int p = 0; p < CHP; p++) {
        int s = p % 3;
        asm volatile("cp.async.wait_group 1;" ::: "memory");
        __syncthreads();
        if (p + 2 < CHP) issue(p + 2, (p + 2) % 3);
        asm volatile("cp.async.commit_group;" ::: "memory");

        const float* hp = hstg + s * (2 * BM);
        const float hA0 = hp[row0],      hA1 = hp[row0 + 8];        // chunk 2p
        const float hB0 = hp[BM + row0], hB1 = hp[BM + row0 + 8];   // chunk 2p+1

        // A fragments: P0 = row g, P1 = row g+8; global k-pair index 0..9
        uint32_t P0[10], P1[10];
#pragma unroll
        for (int pb = 0; pb < 5; pb++) {
            const int ib = pb * 8 + 2 * t4;
            float2 x0 = *(const float2*)(xs + row0 * 40 + ib);
            float2 x1 = *(const float2*)(xs + (row0 + 8) * 40 + ib);
            P0[pb]     = pack_h2(x0.x * hA0, x0.y * hA0);
            P1[pb]     = pack_h2(x1.x * hA1, x1.y * hA1);
            P0[5 + pb] = pack_h2(x0.x * hB0, x0.y * hB0);
            P1[5 + pb] = pack_h2(x1.x * hB1, x1.y * hB1);
        }

        const uint32_t* bs = bstg + s * STG_BW;
#pragma unroll
        for (int q = 0; q < 13; q++) {
            if (q < cnt) {
                const uint4* bw = (const uint4*)(bs + ((nt0 + q) * 32 + lane) * 12);
                uint4 w0 = bw[0], w1 = bw[1], w2 = bw[2];
                mma16(acc[q], P0[0], P1[0], P0[1], P1[1], w0.x, w0.y);
                mma16(acc[q], P0[2], P1[2], P0[3], P1[3], w0.z, w0.w);
                mma16(acc[q], P0[4], P1[4], P0[5], P1[5], w1.x, w1.y);
                mma16(acc[q], P0[6], P1[6], P0[7], P1[7], w1.z, w1.w);
                mma16(acc[q], P0[8], P1[8], P0[9], P1[9], w2.x, w2.y);
            }
        }
    }

    // store (Hout transposed [n][m])
    const int r0 = m0 + row0;
    const int r1 = r0 + 8;
#pragma unroll
    for (int q = 0; q < 13; q++) {
        if (q < cnt) {
            int n0 = (nt0 + q) * 8 + t4 * 2;
            if (r0 < MT) {
                Hout[(size_t)n0 * MT + r0]       = acc[q][0];
                Hout[(size_t)(n0 + 1) * MT + r0] = acc[q][1];
            }
            if (r1 < MT) {
                Hout[(size_t)n0 * MT + r1]       = acc[q][2];
                Hout[(size_t)(n0 + 1) * MT + r1] = acc[q][3];
            }
        }
    }
}

// ---------------------------------------------------------------- reduction
__global__ void reduce_out_kernel(float* __restrict__ out) {
    int idx = blockIdx.x * blockDim.x + threadIdx.x;
    if (idx >= 512 * 600) return;
    int b = idx / 600, no = idx - b * 600;
    const float* H = (no < 200) ? g_Ht1 : (no < 400 ? g_Ht2 : g_Ht3);
    int n = no % 200;
    const float4* p = (const float4*)(H + (size_t)n * MT + b * 32);
    float s = 0.0f;
#pragma unroll
    for (int q = 0; q < 8; q++) {
        float4 v = p[q];
        s += v.x + v.y + v.z + v.w;
    }
    out[idx] = s;
}

// ---------------------------------------------------------------- launch
extern "C" void kernel_launch(void* const* d_in, const int* in_sizes, int n_in,
                              void* d_out, int out_size) {
    const float* inp = (const float*)d_in[0];
    const float* W0  = (const float*)d_in[1];
    const float* W1  = (const float*)d_in[2];
    const float* W2  = (const float*)d_in[3];
    float* out = (float*)d_out;

    void *pXt, *pH1, *pH2, *pH3, *pB0, *pB1, *pB2;
    cudaGetSymbolAddress(&pXt, g_Xt);
    cudaGetSymbolAddress(&pH1, g_Ht1);
    cudaGetSymbolAddress(&pH2, g_Ht2);
    cudaGetSymbolAddress(&pH3, g_Ht3);
    cudaGetSymbolAddress(&pB0, g_B0);
    cudaGetSymbolAddress(&pB1, g_B1);
    cudaGetSymbolAddress(&pB2, g_B2);
    float*    Xt = (float*)pXt;
    float*    H1 = (float*)pH1;
    float*    H2 = (float*)pH2;
    float*    H3 = (float*)pH3;
    uint32_t* B0 = (uint32_t*)pB0;
    uint32_t* B1 = (uint32_t*)pB1;
    uint32_t* B2 = (uint32_t*)pB2;

    const int SMEM = 3 * STG_BB + 17920 + 2688;   // 135808 B
    cudaFuncSetAttribute(cin_fp16_layer<40>,
                         cudaFuncAttributeMaxDynamicSharedMemorySize, SMEM);
    cudaFuncSetAttribute(cin_fp16_layer<200>,
                         cudaFuncAttributeMaxDynamicSharedMemorySize, SMEM);

    transpose_x_kernel<<<(F0 * MT + 255) / 256, 256>>>(inp);

    prep_blob_kernel<<<(20  * STG_BW + 255) / 256, 256>>>(W0, B0, 40,  20);
    prep_blob_kernel<<<(100 * STG_BW + 255) / 256, 256>>>(W1, B1, 200, 100);
    prep_blob_kernel<<<(100 * STG_BW + 255) / 256, 256>>>(W2, B2, 200, 100);

    cin_fp16_layer<40> <<<GRID, 512, SMEM>>>(Xt, B0, H1);
    cin_fp16_layer<200><<<GRID, 512, SMEM>>>(H1, B1, H2);
    cin_fp16_layer<200><<<GRID, 512, SMEM>>>(H2, B2, H3);

    reduce_out_kernel<<<(512 * 600 + 255) / 256, 256>>>(out);
}

// round 8
// speedup vs baseline: 12.1925x; 1.2222x over previous
#include <cuda_runtime.h>
#include <cuda_fp16.h>
#include <cstdint>

// ===========================================================================
// CIN (xDeepFM) on GB300 via mma.sync fp16 (f32 accum).
// Layers 1-2: generated-A GEMM at M=16384 (chunk-paired K=80 = 5 x m16n8k16,
//   147 CTAs / BM=112 / 16 warps, table-balanced per SMSP).
// Layer 3 collapsed: out3[b,n] = sum_k S2[b,k] W2[k,n],
//   S2[b, j*40+i] = sum_d X[b,i,d] H2[b,j,d]  (d-reduction commutes with W2).
//   s2_kernel: per-b scalar dots (f32), one fp16 rounding.
//   final3: M=512 GEMM reusing the SAME W2 blob layout + mainloop fragments.
// ===========================================================================

constexpr int MT  = 16384;
constexpr int F0  = 40;
constexpr int BM  = 112;
constexpr int NT  = 25;

constexpr int STG_BW   = NT * 32 * 12;        // B words per pair-stage = 9600
constexpr int STG_BB   = STG_BW * 4;          // 38400 B
constexpr int GRID     = 147;

__device__ float g_Xt [F0  * MT + 256];
__device__ float g_Ht1[200 * MT + 256];
__device__ float g_Ht2[200 * MT + 256];
__device__ __align__(16) __half g_S2[512 * 8000];
__device__ __align__(16) uint32_t g_B0[20  * STG_BW];
__device__ __align__(16) uint32_t g_B1[100 * STG_BW];
__device__ __align__(16) uint32_t g_B2[100 * STG_BW];

// warp assignment: (m16 tile, nt0, cnt); SMSP sums (wid%4): 45,45,43,42
__constant__ int c_tile[16] = {2,3,4,5, 2,3,6,4, 5,6,0,1, 0,0,1,1};
__constant__ int c_nt0 [16] = {0,0,0,0, 13,13,0,13, 13,13,0,0, 9,17,9,17};
__constant__ int c_cnt [16] = {13,13,13,13, 12,12,13,12, 12,12,9,9, 8,8,8,8};

// ---------------------------------------------------------------- helpers
__device__ __forceinline__ uint32_t smem_u32(const void* p) {
    uint32_t a;
    asm("{ .reg .u64 t; cvta.to.shared.u64 t, %1; cvt.u32.u64 %0, t; }"
        : "=r"(a) : "l"(p));
    return a;
}

__device__ __forceinline__ uint32_t pack_h2(float lo, float hi) {
    uint32_t u;
    asm("cvt.rn.f16x2.f32 %0, %1, %2;" : "=r"(u) : "f"(hi), "f"(lo));
    return u;
}

__device__ __forceinline__ void cp16(uint32_t dst_smem, const void* src) {
    asm volatile("cp.async.cg.shared.global [%0], [%1], 16;"
                 :: "r"(dst_smem), "l"(src) : "memory");
}

__device__ __forceinline__ void mma16(float* d,
                                      uint32_t a0, uint32_t a1, uint32_t a2, uint32_t a3,
                                      uint32_t b0, uint32_t b1) {
    asm volatile(
        "mma.sync.aligned.m16n8k16.row.col.f32.f16.f16.f32 "
        "{%0,%1,%2,%3}, {%4,%5,%6,%7}, {%8,%9}, {%0,%1,%2,%3};"
        : "+f"(d[0]), "+f"(d[1]), "+f"(d[2]), "+f"(d[3])
        : "r"(a0), "r"(a1), "r"(a2), "r"(a3), "r"(b0), "r"(b1));
}

// ---------------------------------------------------------------- prep
__global__ void transpose_x_kernel(const float* __restrict__ inp) {
    int idx = blockIdx.x * blockDim.x + threadIdx.x;
    if (idx >= F0 * MT) return;
    int i = idx >> 14;
    int m = idx & (MT - 1);
    int b = m >> 5, d = m & 31;
    g_Xt[idx] = inp[b * (F0 * 32) + i * 32 + d];
}

// blob[p][nt][lane][v]:  v<5: u=v, j=2p;  5<=v<10: u=v-5, j=2p+1;  else 0.
//   n = nt*8 + (lane>>2);  i0 = u*8 + (lane&3)*2
//   word = h2( W[(i0*FI+j)*200+n], W[((i0+1)*FI+j)*200+n] )
__global__ void prep_blob_kernel(const float* __restrict__ W,
                                 uint32_t* __restrict__ blob, int FI, int NP) {
    int idx = blockIdx.x * blockDim.x + threadIdx.x;
    if (idx >= NP * STG_BW) return;
    int v = idx % 12;
    int t = idx / 12;
    int lane = t & 31; t >>= 5;
    int nt   = t % NT;
    int p    = t / NT;

    uint32_t word = 0;
    if (v < 10) {
        int u = (v < 5) ? v : v - 5;
        int j = 2 * p + (v >= 5);
        int n  = nt * 8 + (lane >> 2);
        int i0 = u * 8 + (lane & 3) * 2;
        float lo = W[((size_t)i0 * FI + j) * 200 + n];
        float hi = W[((size_t)(i0 + 1) * FI + j) * 200 + n];
        word = pack_h2(lo, hi);
    }
    blob[idx] = word;
}

// ---------------------------------------------------------------- layer 1/2
// smem: bstg 3*38400 | xs[BM][40] 17920 | hstg[3][2][BM] 2688  = 135808 B
template <int CH>
__global__ __launch_bounds__(512, 1)
void cin_fp16_layer(const float* __restrict__ Hprev,    // [CH][MT]
                    const uint32_t* __restrict__ blob,  // [CHP][STG_BW]
                    float* __restrict__ Hout)           // [200][MT]
{
    constexpr int CHP = CH / 2;
    extern __shared__ __align__(16) char smem[];
    uint32_t* bstg = (uint32_t*)smem;
    float*    xs   = (float*)(smem + 3 * STG_BB);
    float*    hstg = (float*)(smem + 3 * STG_BB + 17920);

    const int tid  = threadIdx.x;
    const int lane = tid & 31;
    const int wid  = tid >> 5;
    const int g    = lane >> 2;
    const int t4   = lane & 3;
    const int m0   = blockIdx.x * BM;

    const int tile = c_tile[wid];
    const int nt0  = c_nt0[wid];
    const int cnt  = c_cnt[wid];
    const int row0 = tile * 16 + g;

    for (int idx = tid; idx < BM * 40; idx += 512) {
        int ml = idx / 40, i = idx - ml * 40;
        int gr = m0 + ml; if (gr > MT - 1) gr = MT - 1;
        xs[ml * 40 + i] = g_Xt[i * MT + gr];
    }

    const uint32_t uB = smem_u32(bstg);
    const uint32_t uH = smem_u32(hstg);

    auto issue = [&](int p, int s) {
        const char* srcB = (const char*)(blob + (size_t)p * STG_BW);
        uint32_t dB = uB + s * STG_BB;
        for (int t = tid * 16; t < STG_BB; t += 512 * 16)
            cp16(dB + t, srcB + t);
        if (tid < 56) {
            int cc = tid / 28, q = tid - cc * 28;
            cp16(uH + s * (2 * BM * 4) + cc * (BM * 4) + q * 16,
                 (const char*)(Hprev + (size_t)(2 * p + cc) * MT + m0) + q * 16);
        }
    };

    issue(0, 0);
    asm volatile("cp.async.commit_group;" ::: "memory");
    issue(1, 1);
    asm volatile("cp.async.commit_group;" ::: "memory");

    float acc[13][4];
#pragma unroll
    for (int q = 0; q < 13; q++)
#pragma unroll
        for (int c = 0; c < 4; c++) acc[q][c] = 0.0f;

    for (int p = 0; p < CHP; p++) {
        int s = p % 3;
        asm volatile("cp.async.wait_group 1;" ::: "memory");
        __syncthreads();
        if (p + 2 < CHP) issue(p + 2, (p + 2) % 3);
        asm volatile("cp.async.commit_group;" ::: "memory");

        const float* hp = hstg + s * (2 * BM);
        const float hA0 = hp[row0],      hA1 = hp[row0 + 8];
        const float hB0 = hp[BM + row0], hB1 = hp[BM + row0 + 8];

        uint32_t P0[10], P1[10];
#pragma unroll
        for (int pb = 0; pb < 5; pb++) {
            const int ib = pb * 8 + 2 * t4;
            float2 x0 = *(const float2*)(xs + row0 * 40 + ib);
            float2 x1 = *(const float2*)(xs + (row0 + 8) * 40 + ib);
            P0[pb]     = pack_h2(x0.x * hA0, x0.y * hA0);
            P1[pb]     = pack_h2(x1.x * hA1, x1.y * hA1);
            P0[5 + pb] = pack_h2(x0.x * hB0, x0.y * hB0);
            P1[5 + pb] = pack_h2(x1.x * hB1, x1.y * hB1);
        }

        const uint32_t* bs = bstg + s * STG_BW;
#pragma unroll
        for (int q = 0; q < 13; q++) {
            if (q < cnt) {
                const uint4* bw = (const uint4*)(bs + ((nt0 + q) * 32 + lane) * 12);
                uint4 w0 = bw[0], w1 = bw[1], w2 = bw[2];
                mma16(acc[q], P0[0], P1[0], P0[1], P1[1], w0.x, w0.y);
                mma16(acc[q], P0[2], P1[2], P0[3], P1[3], w0.z, w0.w);
                mma16(acc[q], P0[4], P1[4], P0[5], P1[5], w1.x, w1.y);
                mma16(acc[q], P0[6], P1[6], P0[7], P1[7], w1.z, w1.w);
                mma16(acc[q], P0[8], P1[8], P0[9], P1[9], w2.x, w2.y);
            }
        }
    }

    const int r0 = m0 + row0;
    const int r1 = r0 + 8;
#pragma unroll
    for (int q = 0; q < 13; q++) {
        if (q < cnt) {
            int n0 = (nt0 + q) * 8 + t4 * 2;
            if (r0 < MT) {
                Hout[(size_t)n0 * MT + r0]       = acc[q][0];
                Hout[(size_t)(n0 + 1) * MT + r0] = acc[q][1];
            }
            if (r1 < MT) {
                Hout[(size_t)n0 * MT + r1]       = acc[q][2];
                Hout[(size_t)(n0 + 1) * MT + r1] = acc[q][3];
            }
        }
    }
}

// ---------------------------------------------------------------- layer 3
// S2[b, j*40+i] = sum_d X[b,i,d] * H2[b,j,d]  (f32 accum, one fp16 rounding)
__global__ __launch_bounds__(320)
void s2_kernel() {
    __shared__ float h2s[200 * 36];                 // 28800 B (36-pad: no conflicts)
    __shared__ __align__(16) __half s2s[8000];      // 16000 B
    const int b   = blockIdx.x;
    const int tid = threadIdx.x;

    for (int idx = tid; idx < 200 * 32; idx += 320) {
        int j = idx >> 5, d = idx & 31;
        h2s[j * 36 + d] = g_Ht2[(size_t)j * MT + b * 32 + d];
    }
    __syncthreads();

    const int i  = tid >> 3;      // 0..39
    const int jg = tid & 7;
    float4 xr[8];
    const float4* xp = (const float4*)(g_Xt + (size_t)i * MT + b * 32);
#pragma unroll
    for (int q = 0; q < 8; q++) xr[q] = xp[q];

#pragma unroll 5
    for (int q = 0; q < 25; q++) {
        int j = jg + 8 * q;
        const float4* hp = (const float4*)(h2s + j * 36);
        float s = 0.0f;
#pragma unroll
        for (int w = 0; w < 8; w++) {
            float4 h = hp[w];
            s += xr[w].x * h.x + xr[w].y * h.y + xr[w].z * h.z + xr[w].w * h.w;
        }
        s2s[j * 40 + i] = __float2half_rn(s);
    }
    __syncthreads();

    const uint4* ss = (const uint4*)s2s;
    uint4* dd = (uint4*)(g_S2 + (size_t)b * 8000);
    for (int idx = tid; idx < 1000; idx += 320) dd[idx] = ss[idx];
}

// out[b, 400+n] = sum_k S2[b,k] W2[k,n].  32 CTAs (16 b-rows each), 25 warps = nt.
// smem: B stages 3*38400 | A stages 3*16*176 = 123648 B
__global__ __launch_bounds__(800, 1)
void final3_kernel(float* __restrict__ out) {
    constexpr int NP3 = 100;
    constexpr int ARS = 176;                  // A row stride bytes (88 halves)
    extern __shared__ __align__(16) char smem[];
    uint32_t* bstg = (uint32_t*)smem;                 // 3 * 9600 words
    char*     astg = smem + 3 * STG_BB;               // 3 * 2816 B

    const int tid  = threadIdx.x;
    const int lane = tid & 31;
    const int wid  = tid >> 5;                // nt = 0..24
    const int g    = lane >> 2;
    const int t4   = lane & 3;
    const int b0   = blockIdx.x * 16;

    const uint32_t uB = smem_u32(bstg);
    const uint32_t uA = smem_u32(astg);

    auto issue = [&](int p, int s) {
        const char* srcB = (const char*)(g_B2 + (size_t)p * STG_BW);
        uint32_t dB = uB + s * STG_BB;
        for (int t = tid * 16; t < STG_BB; t += 800 * 16)
            cp16(dB + t, srcB + t);
        if (tid < 160) {
            int r = tid / 10, sg = tid - r * 10;
            cp16(uA + s * (16 * ARS) + r * ARS + sg * 16,
                 (const char*)(g_S2 + (size_t)(b0 + r) * 8000 + p * 80) + sg * 16);
        }
    };

    issue(0, 0);
    asm volatile("cp.async.commit_group;" ::: "memory");
    issue(1, 1);
    asm volatile("cp.async.commit_group;" ::: "memory");

    float acc[4] = {0.f, 0.f, 0.f, 0.f};

    for (int p = 0; p < NP3; p++) {
        int s = p % 3;
        asm volatile("cp.async.wait_group 1;" ::: "memory");
        __syncthreads();
        if (p + 2 < NP3) issue(p + 2, (p + 2) % 3);
        asm volatile("cp.async.commit_group;" ::: "memory");

        const char* as = astg + s * (16 * ARS);
        uint32_t P0[10], P1[10];
#pragma unroll
        for (int pb = 0; pb < 10; pb++) {
            P0[pb] = *(const uint32_t*)(as + g * ARS       + (pb * 8 + 2 * t4) * 2);
            P1[pb] = *(const uint32_t*)(as + (g + 8) * ARS + (pb * 8 + 2 * t4) * 2);
        }
        const uint4* bw = (const uint4*)(bstg + s * STG_BW + (wid * 32 + lane) * 12);
        uint4 w0 = bw[0], w1 = bw[1], w2 = bw[2];
        mma16(acc, P0[0], P1[0], P0[1], P1[1], w0.x, w0.y);
        mma16(acc, P0[2], P1[2], P0[3], P1[3], w0.z, w0.w);
        mma16(acc, P0[4], P1[4], P0[5], P1[5], w1.x, w1.y);
        mma16(acc, P0[6], P1[6], P0[7], P1[7], w1.z, w1.w);
        mma16(acc, P0[8], P1[8], P0[9], P1[9], w2.x, w2.y);
    }

    const int n0 = 400 + wid * 8 + t4 * 2;
    out[(size_t)(b0 + g) * 600 + n0]         = acc[0];
    out[(size_t)(b0 + g) * 600 + n0 + 1]     = acc[1];
    out[(size_t)(b0 + g + 8) * 600 + n0]     = acc[2];
    out[(size_t)(b0 + g + 8) * 600 + n0 + 1] = acc[3];
}

// ---------------------------------------------------------------- reduction
__global__ void reduce_out_kernel(float* __restrict__ out) {
    int idx = blockIdx.x * blockDim.x + threadIdx.x;
    if (idx >= 512 * 400) return;
    int b = idx / 400, no = idx - b * 400;
    const float* H = (no < 200) ? g_Ht1 : g_Ht2;
    int n = no % 200;
    const float4* p = (const float4*)(H + (size_t)n * MT + b * 32);
    float s = 0.0f;
#pragma unroll
    for (int q = 0; q < 8; q++) {
        float4 v = p[q];
        s += v.x + v.y + v.z + v.w;
    }
    out[b * 600 + no] = s;
}

// ---------------------------------------------------------------- launch
extern "C" void kernel_launch(void* const* d_in, const int* in_sizes, int n_in,
                              void* d_out, int out_size) {
    const float* inp = (const float*)d_in[0];
    const float* W0  = (const float*)d_in[1];
    const float* W1  = (const float*)d_in[2];
    const float* W2  = (const float*)d_in[3];
    float* out = (float*)d_out;

    void *pXt, *pH1, *pH2, *pB0, *pB1, *pB2;
    cudaGetSymbolAddress(&pXt, g_Xt);
    cudaGetSymbolAddress(&pH1, g_Ht1);
    cudaGetSymbolAddress(&pH2, g_Ht2);
    cudaGetSymbolAddress(&pB0, g_B0);
    cudaGetSymbolAddress(&pB1, g_B1);
    cudaGetSymbolAddress(&pB2, g_B2);
    float*    Xt = (float*)pXt;
    float*    H1 = (float*)pH1;
    float*    H2 = (float*)pH2;
    uint32_t* B0 = (uint32_t*)pB0;
    uint32_t* B1 = (uint32_t*)pB1;
    uint32_t* B2 = (uint32_t*)pB2;

    const int SMEM  = 3 * STG_BB + 17920 + 2688;   // 135808 B
    const int SMEM3 = 3 * STG_BB + 3 * 16 * 176;   // 123648 B
    cudaFuncSetAttribute(cin_fp16_layer<40>,
                         cudaFuncAttributeMaxDynamicSharedMemorySize, SMEM);
    cudaFuncSetAttribute(cin_fp16_layer<200>,
                         cudaFuncAttributeMaxDynamicSharedMemorySize, SMEM);
    cudaFuncSetAttribute(final3_kernel,
                         cudaFuncAttributeMaxDynamicSharedMemorySize, SMEM3);

    transpose_x_kernel<<<(F0 * MT + 255) / 256, 256>>>(inp);

    prep_blob_kernel<<<(20  * STG_BW + 255) / 256, 256>>>(W0, B0, 40,  20);
    prep_blob_kernel<<<(100 * STG_BW + 255) / 256, 256>>>(W1, B1, 200, 100);
    prep_blob_kernel<<<(100 * STG_BW + 255) / 256, 256>>>(W2, B2, 200, 100);

    cin_fp16_layer<40> <<<GRID, 512, SMEM>>>(Xt, B0, H1);
    cin_fp16_layer<200><<<GRID, 512, SMEM>>>(H1, B1, H2);

    s2_kernel<<<512, 320>>>();
    final3_kernel<<<32, 800, SMEM3>>>(out);

    reduce_out_kernel<<<(512 * 400 + 255) / 256, 256>>>(out);
}

// round 9
// speedup vs baseline: 14.5957x; 1.1971x over previous
#include <cuda_runtime.h>
#include <cuda_fp16.h>
#include <cstdint>

// ===========================================================================
// CIN (xDeepFM) on GB300 via mma.sync fp16 (f32 accum).
// Layers 1-2: generated-A GEMM at M=16384 (chunk-paired K=80 = 5 x m16n8k16,
//   147 CTAs / BM=112 / 16 warps, table-balanced per SMSP).
// Layer 3 collapsed: out3[b,n] = sum_k S2[b,k] W2[k,n],
//   S2[b, j*40+i] = sum_d X[b,i,d] H2[b,j,d].
//   final3: M=512 GEMM, 4-way K-split -> 128 CTAs, deterministic f32 partials.
// Prep blobs fused into one kernel; reduce_out sums d-reduction (cols 0-399)
// and the final3 partials (cols 400-599).
// ===========================================================================

constexpr int MT  = 16384;
constexpr int F0  = 40;
constexpr int BM  = 112;
constexpr int NT  = 25;

constexpr int STG_BW   = NT * 32 * 12;        // B words per pair-stage = 9600
constexpr int STG_BB   = STG_BW * 4;          // 38400 B
constexpr int GRID     = 147;

__device__ float g_Xt [F0  * MT + 256];
__device__ float g_Ht1[200 * MT + 256];
__device__ float g_Ht2[200 * MT + 256];
__device__ __align__(16) __half g_S2[512 * 8000];
__device__ float g_P3[4 * 512 * 200];
__device__ __align__(16) uint32_t g_B0[20  * STG_BW];
__device__ __align__(16) uint32_t g_B1[100 * STG_BW];
__device__ __align__(16) uint32_t g_B2[100 * STG_BW];

// warp assignment: (m16 tile, nt0, cnt); SMSP sums (wid%4): 45,45,43,42
__constant__ int c_tile[16] = {2,3,4,5, 2,3,6,4, 5,6,0,1, 0,0,1,1};
__constant__ int c_nt0 [16] = {0,0,0,0, 13,13,0,13, 13,13,0,0, 9,17,9,17};
__constant__ int c_cnt [16] = {13,13,13,13, 12,12,13,12, 12,12,9,9, 8,8,8,8};

// ---------------------------------------------------------------- helpers
__device__ __forceinline__ uint32_t smem_u32(const void* p) {
    uint32_t a;
    asm("{ .reg .u64 t; cvta.to.shared.u64 t, %1; cvt.u32.u64 %0, t; }"
        : "=r"(a) : "l"(p));
    return a;
}

__device__ __forceinline__ uint32_t pack_h2(float lo, float hi) {
    uint32_t u;
    asm("cvt.rn.f16x2.f32 %0, %1, %2;" : "=r"(u) : "f"(hi), "f"(lo));
    return u;
}

__device__ __forceinline__ void cp16(uint32_t dst_smem, const void* src) {
    asm volatile("cp.async.cg.shared.global [%0], [%1], 16;"
                 :: "r"(dst_smem), "l"(src) : "memory");
}

__device__ __forceinline__ void mma16(float* d,
                                      uint32_t a0, uint32_t a1, uint32_t a2, uint32_t a3,
                                      uint32_t b0, uint32_t b1) {
    asm volatile(
        "mma.sync.aligned.m16n8k16.row.col.f32.f16.f16.f32 "
        "{%0,%1,%2,%3}, {%4,%5,%6,%7}, {%8,%9}, {%0,%1,%2,%3};"
        : "+f"(d[0]), "+f"(d[1]), "+f"(d[2]), "+f"(d[3])
        : "r"(a0), "r"(a1), "r"(a2), "r"(a3), "r"(b0), "r"(b1));
}

// ---------------------------------------------------------------- prep
__global__ void transpose_x_kernel(const float* __restrict__ inp) {
    int idx = blockIdx.x * blockDim.x + threadIdx.x;
    if (idx >= F0 * MT) return;
    int i = idx >> 14;
    int m = idx & (MT - 1);
    int b = m >> 5, d = m & 31;
    g_Xt[idx] = inp[b * (F0 * 32) + i * 32 + d];
}

// fused blob prep: pg<20 -> B0(W0,FI=40); pg<120 -> B1(W1,200); else B2(W2,200)
// blob[p][nt][lane][v]:  v<5: u=v, j=2p;  5<=v<10: u=v-5, j=2p+1;  else 0.
//   n = nt*8 + (lane>>2);  i0 = u*8 + (lane&3)*2
__global__ void prep_blob_fused(const float* __restrict__ W0,
                                const float* __restrict__ W1,
                                const float* __restrict__ W2,
                                uint32_t* __restrict__ B0,
                                uint32_t* __restrict__ B1,
                                uint32_t* __restrict__ B2) {
    int idx = blockIdx.x * blockDim.x + threadIdx.x;
    if (idx >= 220 * STG_BW) return;
    int v = idx % 12;
    int t = idx / 12;
    int lane = t & 31; t >>= 5;
    int nt   = t % NT;
    int pg   = t / NT;

    const float* W; uint32_t* blob; int FI, p;
    if (pg < 20)       { W = W0; blob = B0; FI = 40;  p = pg; }
    else if (pg < 120) { W = W1; blob = B1; FI = 200; p = pg - 20; }
    else               { W = W2; blob = B2; FI = 200; p = pg - 120; }

    uint32_t word = 0;
    if (v < 10) {
        int u = (v < 5) ? v : v - 5;
        int j = 2 * p + (v >= 5);
        int n  = nt * 8 + (lane >> 2);
        int i0 = u * 8 + (lane & 3) * 2;
        float lo = __ldg(&W[((size_t)i0 * FI + j) * 200 + n]);
        float hi = __ldg(&W[((size_t)(i0 + 1) * FI + j) * 200 + n]);
        word = pack_h2(lo, hi);
    }
    blob[(((size_t)p * NT + nt) * 32 + lane) * 12 + v] = word;
}

// ---------------------------------------------------------------- layer 1/2
// smem: bstg 3*38400 | xs[BM][40] 17920 | hstg[3][2][BM] 2688  = 135808 B
template <int CH>
__global__ __launch_bounds__(512, 1)
void cin_fp16_layer(const float* __restrict__ Hprev,    // [CH][MT]
                    const uint32_t* __restrict__ blob,  // [CHP][STG_BW]
                    float* __restrict__ Hout)           // [200][MT]
{
    constexpr int CHP = CH / 2;
    extern __shared__ __align__(16) char smem[];
    uint32_t* bstg = (uint32_t*)smem;
    float*    xs   = (float*)(smem + 3 * STG_BB);
    float*    hstg = (float*)(smem + 3 * STG_BB + 17920);

    const int tid  = threadIdx.x;
    const int lane = tid & 31;
    const int wid  = tid >> 5;
    const int g    = lane >> 2;
    const int t4   = lane & 3;
    const int m0   = blockIdx.x * BM;

    const int tile = c_tile[wid];
    const int nt0  = c_nt0[wid];
    const int cnt  = c_cnt[wid];
    const int row0 = tile * 16 + g;

    for (int idx = tid; idx < BM * 40; idx += 512) {
        int ml = idx / 40, i = idx - ml * 40;
        int gr = m0 + ml; if (gr > MT - 1) gr = MT - 1;
        xs[ml * 40 + i] = g_Xt[i * MT + gr];
    }

    const uint32_t uB = smem_u32(bstg);
    const uint32_t uH = smem_u32(hstg);

    auto issue = [&](int p, int s) {
        const char* srcB = (const char*)(blob + (size_t)p * STG_BW);
        uint32_t dB = uB + s * STG_BB;
        for (int t = tid * 16; t < STG_BB; t += 512 * 16)
            cp16(dB + t, srcB + t);
        if (tid < 56) {
            int cc = tid / 28, q = tid - cc * 28;
            cp16(uH + s * (2 * BM * 4) + cc * (BM * 4) + q * 16,
                 (const char*)(Hprev + (size_t)(2 * p + cc) * MT + m0) + q * 16);
        }
    };

    issue(0, 0);
    asm volatile("cp.async.commit_group;" ::: "memory");
    issue(1, 1);
    asm volatile("cp.async.commit_group;" ::: "memory");

    float acc[13][4];
#pragma unroll
    for (int q = 0; q < 13; q++)
#pragma unroll
        for (int c = 0; c < 4; c++) acc[q][c] = 0.0f;

    for (int p = 0; p < CHP; p++) {
        int s = p % 3;
        asm volatile("cp.async.wait_group 1;" ::: "memory");
        __syncthreads();
        if (p + 2 < CHP) issue(p + 2, (p + 2) % 3);
        asm volatile("cp.async.commit_group;" ::: "memory");

        const float* hp = hstg + s * (2 * BM);
        const float hA0 = hp[row0],      hA1 = hp[row0 + 8];
        const float hB0 = hp[BM + row0], hB1 = hp[BM + row0 + 8];

        uint32_t P0[10], P1[10];
#pragma unroll
        for (int pb = 0; pb < 5; pb++) {
            const int ib = pb * 8 + 2 * t4;
            float2 x0 = *(const float2*)(xs + row0 * 40 + ib);
            float2 x1 = *(const float2*)(xs + (row0 + 8) * 40 + ib);
            P0[pb]     = pack_h2(x0.x * hA0, x0.y * hA0);
            P1[pb]     = pack_h2(x1.x * hA1, x1.y * hA1);
            P0[5 + pb] = pack_h2(x0.x * hB0, x0.y * hB0);
            P1[5 + pb] = pack_h2(x1.x * hB1, x1.y * hB1);
        }

        const uint32_t* bs = bstg + s * STG_BW;
#pragma unroll
        for (int q = 0; q < 13; q++) {
            if (q < cnt) {
                const uint4* bw = (const uint4*)(bs + ((nt0 + q) * 32 + lane) * 12);
                uint4 w0 = bw[0], w1 = bw[1], w2 = bw[2];
                mma16(acc[q], P0[0], P1[0], P0[1], P1[1], w0.x, w0.y);
                mma16(acc[q], P0[2], P1[2], P0[3], P1[3], w0.z, w0.w);
                mma16(acc[q], P0[4], P1[4], P0[5], P1[5], w1.x, w1.y);
                mma16(acc[q], P0[6], P1[6], P0[7], P1[7], w1.z, w1.w);
                mma16(acc[q], P0[8], P1[8], P0[9], P1[9], w2.x, w2.y);
            }
        }
    }

    const int r0 = m0 + row0;
    const int r1 = r0 + 8;
#pragma unroll
    for (int q = 0; q < 13; q++) {
        if (q < cnt) {
            int n0 = (nt0 + q) * 8 + t4 * 2;
            if (r0 < MT) {
                Hout[(size_t)n0 * MT + r0]       = acc[q][0];
                Hout[(size_t)(n0 + 1) * MT + r0] = acc[q][1];
            }
            if (r1 < MT) {
                Hout[(size_t)n0 * MT + r1]       = acc[q][2];
                Hout[(size_t)(n0 + 1) * MT + r1] = acc[q][3];
            }
        }
    }
}

// ---------------------------------------------------------------- layer 3
// S2[b, j*40+i] = sum_d X[b,i,d] * H2[b,j,d]  (f32 accum, one fp16 rounding)
__global__ __launch_bounds__(320)
void s2_kernel() {
    __shared__ float h2s[200 * 36];
    __shared__ __align__(16) __half s2s[8000];
    const int b   = blockIdx.x;
    const int tid = threadIdx.x;

    for (int idx = tid; idx < 200 * 32; idx += 320) {
        int j = idx >> 5, d = idx & 31;
        h2s[j * 36 + d] = g_Ht2[(size_t)j * MT + b * 32 + d];
    }
    __syncthreads();

    const int i  = tid >> 3;
    const int jg = tid & 7;
    float4 xr[8];
    const float4* xp = (const float4*)(g_Xt + (size_t)i * MT + b * 32);
#pragma unroll
    for (int q = 0; q < 8; q++) xr[q] = xp[q];

#pragma unroll 5
    for (int q = 0; q < 25; q++) {
        int j = jg + 8 * q;
        const float4* hp = (const float4*)(h2s + j * 36);
        float s = 0.0f;
#pragma unroll
        for (int w = 0; w < 8; w++) {
            float4 h = hp[w];
            s += xr[w].x * h.x + xr[w].y * h.y + xr[w].z * h.z + xr[w].w * h.w;
        }
        s2s[j * 40 + i] = __float2half_rn(s);
    }
    __syncthreads();

    const uint4* ss = (const uint4*)s2s;
    uint4* dd = (uint4*)(g_S2 + (size_t)b * 8000);
    for (int idx = tid; idx < 1000; idx += 320) dd[idx] = ss[idx];
}

// P3[kg][b,n] = sum_{k in group kg} S2[b,k] W2[k,n].
// grid 128: bq = bx>>2 (16 b-rows), kg = bx&3 (25 pairs). 25 warps = nt.
__global__ __launch_bounds__(800, 1)
void final3_kernel() {
    constexpr int ARS = 176;                  // A row stride bytes
    extern __shared__ __align__(16) char smem[];
    uint32_t* bstg = (uint32_t*)smem;
    char*     astg = smem + 3 * STG_BB;

    const int tid  = threadIdx.x;
    const int lane = tid & 31;
    const int wid  = tid >> 5;                // nt
    const int g    = lane >> 2;
    const int t4   = lane & 3;
    const int b0   = (blockIdx.x >> 2) * 16;
    const int kg   = blockIdx.x & 3;
    const int P0g  = kg * 25;

    const uint32_t uB = smem_u32(bstg);
    const uint32_t uA = smem_u32(astg);

    auto issue = [&](int pl, int s) {
        int p = P0g + pl;
        const char* srcB = (const char*)(g_B2 + (size_t)p * STG_BW);
        uint32_t dB = uB + s * STG_BB;
        for (int t = tid * 16; t < STG_BB; t += 800 * 16)
            cp16(dB + t, srcB + t);
        if (tid < 160) {
            int r = tid / 10, sg = tid - r * 10;
            cp16(uA + s * (16 * ARS) + r * ARS + sg * 16,
                 (const char*)(g_S2 + (size_t)(b0 + r) * 8000 + p * 80) + sg * 16);
        }
    };

    issue(0, 0);
    asm volatile("cp.async.commit_group;" ::: "memory");
    issue(1, 1);
    asm volatile("cp.async.commit_group;" ::: "memory");

    float acc[4] = {0.f, 0.f, 0.f, 0.f};

    for (int pl = 0; pl < 25; pl++) {
        int s = pl % 3;
        asm volatile("cp.async.wait_group 1;" ::: "memory");
        __syncthreads();
        if (pl + 2 < 25) issue(pl + 2, (pl + 2) % 3);
        asm volatile("cp.async.commit_group;" ::: "memory");

        const char* as = astg + s * (16 * ARS);
        uint32_t P0[10], P1[10];
#pragma unroll
        for (int pb = 0; pb < 10; pb++) {
            P0[pb] = *(const uint32_t*)(as + g * ARS       + (pb * 8 + 2 * t4) * 2);
            P1[pb] = *(const uint32_t*)(as + (g + 8) * ARS + (pb * 8 + 2 * t4) * 2);
        }
        const uint4* bw = (const uint4*)(bstg + s * STG_BW + (wid * 32 + lane) * 12);
        uint4 w0 = bw[0], w1 = bw[1], w2 = bw[2];
        mma16(acc, P0[0], P1[0], P0[1], P1[1], w0.x, w0.y);
        mma16(acc, P0[2], P1[2], P0[3], P1[3], w0.z, w0.w);
        mma16(acc, P0[4], P1[4], P0[5], P1[5], w1.x, w1.y);
        mma16(acc, P0[6], P1[6], P0[7], P1[7], w1.z, w1.w);
        mma16(acc, P0[8], P1[8], P0[9], P1[9], w2.x, w2.y);
    }

    const int n0 = wid * 8 + t4 * 2;
    float* P = g_P3 + (size_t)kg * 512 * 200;
    P[(size_t)(b0 + g) * 200 + n0]         = acc[0];
    P[(size_t)(b0 + g) * 200 + n0 + 1]     = acc[1];
    P[(size_t)(b0 + g + 8) * 200 + n0]     = acc[2];
    P[(size_t)(b0 + g + 8) * 200 + n0 + 1] = acc[3];
}

// ---------------------------------------------------------------- reduction
__global__ void reduce_out_kernel(float* __restrict__ out) {
    int idx = blockIdx.x * blockDim.x + threadIdx.x;
    if (idx >= 512 * 600) return;
    int b = idx / 600, no = idx - b * 600;
    float s = 0.0f;
    if (no < 400) {
        const float* H = (no < 200) ? g_Ht1 : g_Ht2;
        int n = no % 200;
        const float4* p = (const float4*)(H + (size_t)n * MT + b * 32);
#pragma unroll
        for (int q = 0; q < 8; q++) {
            float4 v = p[q];
            s += v.x + v.y + v.z + v.w;
        }
    } else {
        int n = no - 400;
#pragma unroll
        for (int kg = 0; kg < 4; kg++)
            s += g_P3[(size_t)kg * 512 * 200 + (size_t)b * 200 + n];
    }
    out[idx] = s;
}

// ---------------------------------------------------------------- launch
extern "C" void kernel_launch(void* const* d_in, const int* in_sizes, int n_in,
                              void* d_out, int out_size) {
    const float* inp = (const float*)d_in[0];
    const float* W0  = (const float*)d_in[1];
    const float* W1  = (const float*)d_in[2];
    const float* W2  = (const float*)d_in[3];
    float* out = (float*)d_out;

    void *pXt, *pH1, *pH2, *pB0, *pB1, *pB2;
    cudaGetSymbolAddress(&pXt, g_Xt);
    cudaGetSymbolAddress(&pH1, g_Ht1);
    cudaGetSymbolAddress(&pH2, g_Ht2);
    cudaGetSymbolAddress(&pB0, g_B0);
    cudaGetSymbolAddress(&pB1, g_B1);
    cudaGetSymbolAddress(&pB2, g_B2);
    float*    Xt = (float*)pXt;
    float*    H1 = (float*)pH1;
    float*    H2 = (float*)pH2;
    uint32_t* B0 = (uint32_t*)pB0;
    uint32_t* B1 = (uint32_t*)pB1;
    uint32_t* B2 = (uint32_t*)pB2;

    const int SMEM  = 3 * STG_BB + 17920 + 2688;   // 135808 B
    const int SMEM3 = 3 * STG_BB + 3 * 16 * 176;   // 123648 B
    cudaFuncSetAttribute(cin_fp16_layer<40>,
                         cudaFuncAttributeMaxDynamicSharedMemorySize, SMEM);
    cudaFuncSetAttribute(cin_fp16_layer<200>,
                         cudaFuncAttributeMaxDynamicSharedMemorySize, SMEM);
    cudaFuncSetAttribute(final3_kernel,
                         cudaFuncAttributeMaxDynamicSharedMemorySize, SMEM3);

    transpose_x_kernel<<<(F0 * MT + 255) / 256, 256>>>(inp);
    prep_blob_fused<<<(220 * STG_BW + 255) / 256, 256>>>(W0, W1, W2, B0, B1, B2);

    cin_fp16_layer<40> <<<GRID, 512, SMEM>>>(Xt, B0, H1);
    cin_fp16_layer<200><<<GRID, 512, SMEM>>>(H1, B1, H2);

    s2_kernel<<<512, 320>>>();
    final3_kernel<<<128, 800, SMEM3>>>();

    reduce_out_kernel<<<(512 * 600 + 255) / 256, 256>>>(out);
}